// round 1
// baseline (speedup 1.0000x reference)
#include <cuda_runtime.h>
#include <math.h>

#define BATCH 500
#define TSTEPS 256
#define EMB 512
#define HID 512
#define GATES 2048   // 4*HID
#define NOUT 100

// Scratch (device globals — allocation-free rule)
__device__ float g_gates[BATCH * GATES];              // 4.1 MB
__device__ float g_c[BATCH * HID];                    // 1 MB
__device__ float g_h0[BATCH * HID];                   // zero h (t=0)
__device__ float g_hall[(size_t)TSTEPS * BATCH * HID]; // 262 MB: h for every step

__device__ __forceinline__ float fast_sigmoid(float x) {
    return 1.f / (1.f + __expf(-x));
}
__device__ __forceinline__ float fast_tanh(float x) {
    float ax = fabsf(x);
    float t = __expf(-2.f * ax);
    float r = (1.f - t) / (1.f + t);
    return copysignf(r, x);
}

__global__ void zero_state_kernel() {
    int idx = blockIdx.x * blockDim.x + threadIdx.x;
    if (idx < BATCH * HID) {
        g_c[idx] = 0.f;
        g_h0[idx] = 0.f;
    }
}

// -------------------------------------------------------------------------
// Per-step gate GEMM with K-concatenation:
// gates[b][n] = sum_{k<512} x_t[b][k] * W_ih[n][k]
//            + sum_{k<512} h_{t-1}[b][k] * W_hh[n][k] + b_ih[n] + b_hh[n]
// Tiling: BM=64, BN=128, BK=16, 256 threads, each thread 4x8 outputs.
// -------------------------------------------------------------------------
__global__ __launch_bounds__(256) void gates_gemm_kernel(
    const float* __restrict__ inp,   // [B][T*E]
    const float* __restrict__ Wih,   // [2048][512]
    const float* __restrict__ Whh,   // [2048][512]
    const float* __restrict__ bih,
    const float* __restrict__ bhh,
    int t)
{
    __shared__ float As[16][64];
    __shared__ float Ws[16][128];

    const int tid = threadIdx.x;
    const int tx = tid & 15;      // N direction (x8)
    const int ty = tid >> 4;      // M direction (x4)
    const int row0 = blockIdx.x * 64;
    const int col0 = blockIdx.y * 128;

    // A-tile load mapping: 64 rows x 16 k; each thread one float4 along k
    const int arow = tid >> 2;
    const int ak   = (tid & 3) * 4;
    // W-tile load mapping: 128 rows(n) x 16 k; each thread two float4
    const int wn = tid >> 1;
    const int wk = (tid & 1) * 8;

    const float* hprev = (t == 0) ? g_h0
                                  : (g_hall + (size_t)(t - 1) * BATCH * HID);
    const float* xbase = inp + (size_t)t * EMB;   // per-row stride T*E

    float acc[4][8];
#pragma unroll
    for (int i = 0; i < 4; i++)
#pragma unroll
        for (int j = 0; j < 8; j++) acc[i][j] = 0.f;

    for (int k0 = 0; k0 < 1024; k0 += 16) {
        const float* Ap;
        size_t astride;
        const float* Wp;
        if (k0 < 512) { Ap = xbase + k0; astride = (size_t)TSTEPS * EMB; Wp = Wih + k0; }
        else          { Ap = hprev + (k0 - 512); astride = HID;          Wp = Whh + (k0 - 512); }

        // load A tile (guard M edge)
        int gr = row0 + arow;
        float4 av = make_float4(0.f, 0.f, 0.f, 0.f);
        if (gr < BATCH) av = *(const float4*)(Ap + (size_t)gr * astride + ak);
        As[ak + 0][arow] = av.x;
        As[ak + 1][arow] = av.y;
        As[ak + 2][arow] = av.z;
        As[ak + 3][arow] = av.w;

        // load W tile (N=2048 exact, no guard)
        const float* wrow = Wp + (size_t)(col0 + wn) * 512 + wk;
        float4 w0 = *(const float4*)(wrow);
        float4 w1 = *(const float4*)(wrow + 4);
        Ws[wk + 0][wn] = w0.x; Ws[wk + 1][wn] = w0.y;
        Ws[wk + 2][wn] = w0.z; Ws[wk + 3][wn] = w0.w;
        Ws[wk + 4][wn] = w1.x; Ws[wk + 5][wn] = w1.y;
        Ws[wk + 6][wn] = w1.z; Ws[wk + 7][wn] = w1.w;

        __syncthreads();

#pragma unroll
        for (int kk = 0; kk < 16; kk++) {
            float a[4], w[8];
            *(float4*)(a)     = *(const float4*)&As[kk][ty * 4];
            *(float4*)(w)     = *(const float4*)&Ws[kk][tx * 8];
            *(float4*)(w + 4) = *(const float4*)&Ws[kk][tx * 8 + 4];
#pragma unroll
            for (int i = 0; i < 4; i++)
#pragma unroll
                for (int j = 0; j < 8; j++) acc[i][j] += a[i] * w[j];
        }
        __syncthreads();
    }

    // epilogue: add biases, store
    const int col = col0 + tx * 8;
    float bias[8];
#pragma unroll
    for (int j = 0; j < 8; j++) bias[j] = bih[col + j] + bhh[col + j];

#pragma unroll
    for (int i = 0; i < 4; i++) {
        int r = row0 + ty * 4 + i;
        if (r < BATCH) {
            float* dst = g_gates + (size_t)r * GATES + col;
#pragma unroll
            for (int j = 0; j < 8; j++) dst[j] = acc[i][j] + bias[j];
        }
    }
}

// -------------------------------------------------------------------------
// Elementwise LSTM cell update: c,h from gates; h written to g_hall[t]
// -------------------------------------------------------------------------
__global__ void lstm_update_kernel(int t) {
    int idx = blockIdx.x * blockDim.x + threadIdx.x;
    if (idx >= BATCH * HID) return;
    int b = idx / HID;
    int j = idx - b * HID;
    const float* g = g_gates + (size_t)b * GATES;
    float ig = fast_sigmoid(g[j]);
    float fg = fast_sigmoid(g[j + 512]);
    float gg = fast_tanh(g[j + 1024]);
    float og = fast_sigmoid(g[j + 1536]);
    float c = fg * g_c[idx] + ig * gg;
    g_c[idx] = c;
    g_hall[(size_t)t * BATCH * HID + idx] = og * fast_tanh(c);
}

// -------------------------------------------------------------------------
// Final FC over ALL steps at once: out[b][t][o] = sigmoid(h_all[t][b] . W_fc[o] + b_fc[o])
// M = T*B = 128000 (rows of g_hall, contiguous), N = 100 (single 128 tile), K = 512
// -------------------------------------------------------------------------
__global__ __launch_bounds__(256) void fc_gemm_kernel(
    const float* __restrict__ Wfc,   // [100][512]
    const float* __restrict__ bfc,   // [100]
    float* __restrict__ out)         // [B][T][100]
{
    __shared__ float As[16][64];
    __shared__ float Ws[16][128];

    const int tid = threadIdx.x;
    const int tx = tid & 15;
    const int ty = tid >> 4;
    const int row0 = blockIdx.x * 64;   // 2000 blocks, exact cover of 128000

    const int arow = tid >> 2;
    const int ak   = (tid & 3) * 4;
    const int wn = tid >> 1;
    const int wk = (tid & 1) * 8;

    float acc[4][8];
#pragma unroll
    for (int i = 0; i < 4; i++)
#pragma unroll
        for (int j = 0; j < 8; j++) acc[i][j] = 0.f;

    for (int k0 = 0; k0 < 512; k0 += 16) {
        // A tile from g_hall (rows exact, no guard)
        const float* Ap = g_hall + (size_t)(row0 + arow) * HID + k0 + ak;
        float4 av = *(const float4*)Ap;
        As[ak + 0][arow] = av.x;
        As[ak + 1][arow] = av.y;
        As[ak + 2][arow] = av.z;
        As[ak + 3][arow] = av.w;

        // W tile, guard n < 100
        float4 w0 = make_float4(0.f, 0.f, 0.f, 0.f);
        float4 w1 = make_float4(0.f, 0.f, 0.f, 0.f);
        if (wn < NOUT) {
            const float* wrow = Wfc + (size_t)wn * 512 + k0 + wk;
            w0 = *(const float4*)(wrow);
            w1 = *(const float4*)(wrow + 4);
        }
        Ws[wk + 0][wn] = w0.x; Ws[wk + 1][wn] = w0.y;
        Ws[wk + 2][wn] = w0.z; Ws[wk + 3][wn] = w0.w;
        Ws[wk + 4][wn] = w1.x; Ws[wk + 5][wn] = w1.y;
        Ws[wk + 6][wn] = w1.z; Ws[wk + 7][wn] = w1.w;

        __syncthreads();

#pragma unroll
        for (int kk = 0; kk < 16; kk++) {
            float a[4], w[8];
            *(float4*)(a)     = *(const float4*)&As[kk][ty * 4];
            *(float4*)(w)     = *(const float4*)&Ws[kk][tx * 8];
            *(float4*)(w + 4) = *(const float4*)&Ws[kk][tx * 8 + 4];
#pragma unroll
            for (int i = 0; i < 4; i++)
#pragma unroll
                for (int j = 0; j < 8; j++) acc[i][j] += a[i] * w[j];
        }
        __syncthreads();
    }

    const int col = tx * 8;
#pragma unroll
    for (int i = 0; i < 4; i++) {
        int r = row0 + ty * 4 + i;      // r = t*BATCH + b
        int tt = r / BATCH;
        int bb = r - tt * BATCH;
        float* dst = out + ((size_t)bb * TSTEPS + tt) * NOUT;
#pragma unroll
        for (int j = 0; j < 8; j++) {
            int c = col + j;
            if (c < NOUT) dst[c] = fast_sigmoid(acc[i][j] + bfc[c]);
        }
    }
}

extern "C" void kernel_launch(void* const* d_in, const int* in_sizes, int n_in,
                              void* d_out, int out_size) {
    const float* inp  = (const float*)d_in[0];  // (500, 1, 256*512)
    const float* Wih  = (const float*)d_in[1];  // (2048, 512)
    const float* Whh  = (const float*)d_in[2];  // (2048, 512)
    const float* bih  = (const float*)d_in[3];  // (2048,)
    const float* bhh  = (const float*)d_in[4];  // (2048,)
    const float* Wfc  = (const float*)d_in[5];  // (100, 512)
    const float* bfc  = (const float*)d_in[6];  // (100,)
    float* out = (float*)d_out;                 // (500, 256, 100)

    // zero c and h0
    zero_state_kernel<<<(BATCH * HID + 255) / 256, 256>>>();

    dim3 ggrid(8, 16);   // ceil(500/64) x 2048/128
    for (int t = 0; t < TSTEPS; t++) {
        gates_gemm_kernel<<<ggrid, 256>>>(inp, Wih, Whh, bih, bhh, t);
        lstm_update_kernel<<<(BATCH * HID + 255) / 256, 256>>>(t);
    }

    fc_gemm_kernel<<<2000, 256>>>(Wfc, bfc, out);
}

// round 3
// speedup vs baseline: 3.6003x; 3.6003x over previous
#include <cuda_runtime.h>
#include <math.h>
#include <stdint.h>

#define BATCH 500
#define TSTEPS 256
#define EMB 512
#define HID 512
#define NOUT 100
#define TBSTRIDE (TSTEPS * EMB)

// step-kernel tiling
#define BM 128
#define BN 64
#define BK 32
#define NSTAGE 32          // K=1024 / BK
#define THREADS 256
#define SA 36              // smem row stride in floats (conflict-free: bank=4g+t)
#define ASZ (BM * SA)      // 4608 floats
#define BSZ (BN * SA)      // 2304 floats
#define SMEM_FLOATS (2 * ASZ + 2 * BSZ)   // 13824
#define SMEM_BYTES (SMEM_FLOATS * 4)      // 55296

// ------------------------- device globals (scratch) -------------------------
__device__ float g_c[BATCH * HID];
__device__ float g_h0[BATCH * HID];
__device__ float g_hall[(size_t)TSTEPS * BATCH * HID];   // 262MB
__device__ uint32_t g_W[2048 * 1024];   // permuted, K-concat, tf32-rounded weights
__device__ float g_pb[2048];            // permuted bias (bih+bhh)

__device__ __forceinline__ float fast_sigmoid(float x) {
    return 1.f / (1.f + __expf(-x));
}
__device__ __forceinline__ float fast_tanh(float x) {
    float ax = fabsf(x);
    float e = __expf(-2.f * ax);
    float r = (1.f - e) / (1.f + e);
    return copysignf(r, x);
}
__device__ __forceinline__ uint32_t to_tf32(float f) {
    uint32_t u;
    asm("cvt.rna.tf32.f32 %0, %1;" : "=r"(u) : "f"(f));
    return u;
}

// ------------------------- init kernels -------------------------
__global__ void zero_state_kernel() {
    int idx = blockIdx.x * blockDim.x + threadIdx.x;
    if (idx < BATCH * HID) {
        g_c[idx] = 0.f;
        g_h0[idx] = 0.f;
    }
}

// Build permuted tf32 weights: row n' = j*4 + gate  <->  n = gate*512 + j
// cols: k<512 from Wih, k>=512 from Whh.  Also permuted bias.
__global__ void prep_weights_kernel(const float* __restrict__ Wih,
                                    const float* __restrict__ Whh,
                                    const float* __restrict__ bih,
                                    const float* __restrict__ bhh) {
    int idx = blockIdx.x * blockDim.x + threadIdx.x;   // 0 .. 2M-1
    int np = idx >> 10;
    int k  = idx & 1023;
    int j = np >> 2, gate = np & 3;
    int n = gate * HID + j;
    float v = (k < EMB) ? Wih[(size_t)n * EMB + k]
                        : Whh[(size_t)n * HID + (k - EMB)];
    g_W[idx] = to_tf32(v);
    if (idx < 2048) {
        int jj = idx >> 2, gg = idx & 3;
        g_pb[idx] = bih[gg * HID + jj] + bhh[gg * HID + jj];
    }
}

// -------------------------------------------------------------------------
// Fused per-step kernel: tf32 mma.sync GEMM (all 4 gates) + LSTM cell update.
// Grid (4, 32): 4 m-tiles of 128 batch rows x 32 tiles of 16 hidden units
// (64 permuted gate columns). A = [x_t | h_{t-1}] streamed K-major.
// -------------------------------------------------------------------------
__global__ __launch_bounds__(THREADS) void lstm_step_kernel(
    const float* __restrict__ inp, int t)
{
    extern __shared__ float sm[];
    const int tid = threadIdx.x;
    const int lid = tid & 31, wid = tid >> 5;
    const int g = lid >> 2, tg = lid & 3;
    const int mw = wid & 3, nw = wid >> 2;     // 4x2 warp grid
    const int m0 = blockIdx.x * BM;
    const int n0 = blockIdx.y * BN;
    const float* hprev = (t == 0) ? g_h0 : g_hall + (size_t)(t - 1) * BATCH * HID;

    float acc[2][4][4];
#pragma unroll
    for (int mf = 0; mf < 2; mf++)
#pragma unroll
        for (int nf = 0; nf < 4; nf++)
#pragma unroll
            for (int r = 0; r < 4; r++) acc[mf][nf][r] = 0.f;

    auto load_stage = [&](int s) {
        const int buf = s & 1;
        const int k0 = s * BK;
        float* As = sm + buf * ASZ;
        float* Bs = sm + 2 * ASZ + buf * BSZ;
        // A tile: 128 rows x 8 float4
#pragma unroll
        for (int it = 0; it < 4; it++) {
            int idx = tid + THREADS * it;
            int r = idx >> 3, c4 = idx & 7;
            int b = m0 + r;
            const float* src = (k0 < EMB)
                ? inp + (size_t)b * TBSTRIDE + (size_t)t * EMB + k0 + c4 * 4
                : hprev + (size_t)b * HID + (k0 - EMB) + c4 * 4;
            uint32_t dst = (uint32_t)__cvta_generic_to_shared(As + r * SA + c4 * 4);
            unsigned sz = (b < BATCH) ? 16u : 0u;
            asm volatile("cp.async.cg.shared.global [%0], [%1], 16, %2;"
                         :: "r"(dst), "l"(src), "r"(sz));
        }
        // B tile: 64 rows x 8 float4 (already tf32 bits)
#pragma unroll
        for (int it = 0; it < 2; it++) {
            int idx = tid + THREADS * it;
            int r = idx >> 3, c4 = idx & 7;
            const uint32_t* src = g_W + (size_t)(n0 + r) * 1024 + k0 + c4 * 4;
            uint32_t dst = (uint32_t)__cvta_generic_to_shared(Bs + r * SA + c4 * 4);
            asm volatile("cp.async.cg.shared.global [%0], [%1], 16;"
                         :: "r"(dst), "l"(src));
        }
        asm volatile("cp.async.commit_group;" ::: "memory");
    };

    load_stage(0);

#pragma unroll 1
    for (int s = 0; s < NSTAGE; s++) {
        if (s + 1 < NSTAGE) {
            load_stage(s + 1);
            asm volatile("cp.async.wait_group 1;" ::: "memory");
        } else {
            asm volatile("cp.async.wait_group 0;" ::: "memory");
        }
        __syncthreads();

        const int buf = s & 1;
        const float* As = sm + buf * ASZ + (mw * 32) * SA;
        const float* Bs = sm + 2 * ASZ + buf * BSZ + (nw * 32) * SA;

#pragma unroll
        for (int kk = 0; kk < 4; kk++) {
            const int k = kk * 8;
            uint32_t a[2][4];
#pragma unroll
            for (int mf = 0; mf < 2; mf++) {
                const float* ap = As + (mf * 16 + g) * SA + k + tg;
                a[mf][0] = to_tf32(ap[0]);
                a[mf][1] = to_tf32(ap[8 * SA]);
                a[mf][2] = to_tf32(ap[4]);
                a[mf][3] = to_tf32(ap[8 * SA + 4]);
            }
            uint32_t bfr[4][2];
#pragma unroll
            for (int nf = 0; nf < 4; nf++) {
                const float* bp = Bs + (nf * 8 + g) * SA + k + tg;
                bfr[nf][0] = __float_as_uint(bp[0]);
                bfr[nf][1] = __float_as_uint(bp[4]);
            }
#pragma unroll
            for (int mf = 0; mf < 2; mf++)
#pragma unroll
                for (int nf = 0; nf < 4; nf++) {
                    asm volatile(
                        "mma.sync.aligned.m16n8k8.row.col.f32.tf32.tf32.f32 "
                        "{%0,%1,%2,%3}, {%4,%5,%6,%7}, {%8,%9}, {%0,%1,%2,%3};"
                        : "+f"(acc[mf][nf][0]), "+f"(acc[mf][nf][1]),
                          "+f"(acc[mf][nf][2]), "+f"(acc[mf][nf][3])
                        : "r"(a[mf][0]), "r"(a[mf][1]), "r"(a[mf][2]), "r"(a[mf][3]),
                          "r"(bfr[nf][0]), "r"(bfr[nf][1]));
                }
        }
        __syncthreads();
    }

    // ---- epilogue: dump accums to smem, then fused LSTM cell update ----
    float* Gs = sm;   // [128][68], 8704 floats (fits in 13824)
#pragma unroll
    for (int mf = 0; mf < 2; mf++)
#pragma unroll
        for (int nf = 0; nf < 4; nf++) {
            int r0 = mw * 32 + mf * 16 + g;
            int c = nw * 32 + nf * 8 + 2 * tg;
            float2 lo = make_float2(acc[mf][nf][0], acc[mf][nf][1]);
            float2 hi = make_float2(acc[mf][nf][2], acc[mf][nf][3]);
            *(float2*)&Gs[r0 * 68 + c] = lo;
            *(float2*)&Gs[(r0 + 8) * 68 + c] = hi;
        }
    __syncthreads();

    const int bl = tid & 127;
    const int jh = tid >> 7;            // 0/1: which 8-wide j half
    const int b = m0 + bl;
    if (b < BATCH) {
        const int j0 = blockIdx.y * 16 + jh * 8;   // global hidden index base
        float cold[8], cnew[8], hval[8];
        *(float4*)&cold[0] = *(const float4*)&g_c[(size_t)b * HID + j0];
        *(float4*)&cold[4] = *(const float4*)&g_c[(size_t)b * HID + j0 + 4];
#pragma unroll
        for (int jj = 0; jj < 8; jj++) {
            int jl = jh * 8 + jj;                  // local col group in [0,16)
            float4 gv = *(float4*)&Gs[bl * 68 + jl * 4];
            float4 pb = *(const float4*)&g_pb[n0 + jl * 4];
            float ig = fast_sigmoid(gv.x + pb.x);
            float fg = fast_sigmoid(gv.y + pb.y);
            float gt = fast_tanh(gv.z + pb.z);
            float og = fast_sigmoid(gv.w + pb.w);
            float c = fg * cold[jj] + ig * gt;
            cnew[jj] = c;
            hval[jj] = og * fast_tanh(c);
        }
        *(float4*)&g_c[(size_t)b * HID + j0]     = *(float4*)&cnew[0];
        *(float4*)&g_c[(size_t)b * HID + j0 + 4] = *(float4*)&cnew[4];
        float* hdst = g_hall + (size_t)t * BATCH * HID + (size_t)b * HID + j0;
        *(float4*)&hdst[0] = *(float4*)&hval[0];
        *(float4*)&hdst[4] = *(float4*)&hval[4];
    }
}

// -------------------------------------------------------------------------
// Final FC over ALL steps: out[b][t][o] = sigmoid(h_all[t][b] . W_fc[o] + b_fc[o])
// M = 128000 rows of g_hall, N = 100, K = 512 (SIMT fp32)
// -------------------------------------------------------------------------
__global__ __launch_bounds__(256) void fc_gemm_kernel(
    const float* __restrict__ Wfc,
    const float* __restrict__ bfc,
    float* __restrict__ out)
{
    __shared__ float As[16][64];
    __shared__ float Ws[16][128];

    const int tid = threadIdx.x;
    const int tx = tid & 15;
    const int ty = tid >> 4;
    const int row0 = blockIdx.x * 64;

    const int arow = tid >> 2;
    const int ak   = (tid & 3) * 4;
    const int wn = tid >> 1;
    const int wk = (tid & 1) * 8;

    float acc[4][8];
#pragma unroll
    for (int i = 0; i < 4; i++)
#pragma unroll
        for (int j = 0; j < 8; j++) acc[i][j] = 0.f;

    for (int k0 = 0; k0 < 512; k0 += 16) {
        const float* Ap = g_hall + (size_t)(row0 + arow) * HID + k0 + ak;
        float4 av = *(const float4*)Ap;
        As[ak + 0][arow] = av.x;
        As[ak + 1][arow] = av.y;
        As[ak + 2][arow] = av.z;
        As[ak + 3][arow] = av.w;

        float4 w0 = make_float4(0.f, 0.f, 0.f, 0.f);
        float4 w1 = make_float4(0.f, 0.f, 0.f, 0.f);
        if (wn < NOUT) {
            const float* wrow = Wfc + (size_t)wn * 512 + k0 + wk;
            w0 = *(const float4*)(wrow);
            w1 = *(const float4*)(wrow + 4);
        }
        Ws[wk + 0][wn] = w0.x; Ws[wk + 1][wn] = w0.y;
        Ws[wk + 2][wn] = w0.z; Ws[wk + 3][wn] = w0.w;
        Ws[wk + 4][wn] = w1.x; Ws[wk + 5][wn] = w1.y;
        Ws[wk + 6][wn] = w1.z; Ws[wk + 7][wn] = w1.w;

        __syncthreads();

#pragma unroll
        for (int kk = 0; kk < 16; kk++) {
            float a[4], w[8];
            *(float4*)(a)     = *(const float4*)&As[kk][ty * 4];
            *(float4*)(w)     = *(const float4*)&Ws[kk][tx * 8];
            *(float4*)(w + 4) = *(const float4*)&Ws[kk][tx * 8 + 4];
#pragma unroll
            for (int i = 0; i < 4; i++)
#pragma unroll
                for (int j = 0; j < 8; j++) acc[i][j] += a[i] * w[j];
        }
        __syncthreads();
    }

    const int col = tx * 8;
#pragma unroll
    for (int i = 0; i < 4; i++) {
        int r = row0 + ty * 4 + i;      // r = t*BATCH + b
        int tt = r / BATCH;
        int bb = r - tt * BATCH;
        float* dst = out + ((size_t)bb * TSTEPS + tt) * NOUT;
#pragma unroll
        for (int j = 0; j < 8; j++) {
            int c = col + j;
            if (c < NOUT) dst[c] = fast_sigmoid(acc[i][j] + bfc[c]);
        }
    }
}

// -------------------------------------------------------------------------
extern "C" void kernel_launch(void* const* d_in, const int* in_sizes, int n_in,
                              void* d_out, int out_size) {
    const float* inp  = (const float*)d_in[0];
    const float* Wih  = (const float*)d_in[1];
    const float* Whh  = (const float*)d_in[2];
    const float* bih  = (const float*)d_in[3];
    const float* bhh  = (const float*)d_in[4];
    const float* Wfc  = (const float*)d_in[5];
    const float* bfc  = (const float*)d_in[6];
    float* out = (float*)d_out;

    cudaFuncSetAttribute(lstm_step_kernel,
                         cudaFuncAttributeMaxDynamicSharedMemorySize, SMEM_BYTES);

    zero_state_kernel<<<(BATCH * HID + 255) / 256, 256>>>();
    prep_weights_kernel<<<(2048 * 1024) / 256, 256>>>(Wih, Whh, bih, bhh);

    dim3 grid(4, 32);
    for (int t = 0; t < TSTEPS; t++) {
        lstm_step_kernel<<<grid, THREADS, SMEM_BYTES>>>(inp, t);
    }

    fc_gemm_kernel<<<2000, 256>>>(Wfc, bfc, out);
}

// round 6
// speedup vs baseline: 6.0381x; 1.6771x over previous
#include <cuda_runtime.h>
#include <cuda_bf16.h>
#include <math.h>
#include <stdint.h>

#define BATCH 500
#define BPAD 512
#define TSTEPS 256
#define EMB 512
#define HID 512
#define NOUT 100
#define TBSTRIDE (TSTEPS * EMB)
#define MROWS (TSTEPS * BPAD)        // 131072 rows of xbf / xg

// ------------------------- device globals (scratch) -------------------------
__device__ __nv_bfloat16 g_xbf[(size_t)MROWS * EMB];        // 134MB  [t*512+b][e]
__device__ __nv_bfloat16 g_Wx[2048 * 512];                  // permuted Wih bf16
__device__ __nv_bfloat16 g_Wh[2048 * 512];                  // permuted Whh bf16
__device__ float g_pb[2048];                                // permuted bias
__device__ float g_xg[(size_t)MROWS * 2048];                // 1.07GB xg fp32
__device__ float g_hall[(size_t)TSTEPS * BATCH * HID];      // 262MB fp32 h
__device__ __nv_bfloat16 g_hb[(size_t)TSTEPS * BPAD * HID]; // 134MB bf16 h, t-indexed
__device__ __nv_bfloat16 g_hz[BPAD * HID];                  // zero h slab for t=0
__device__ unsigned g_bar[4];                               // per-m-group counters

__device__ __forceinline__ float fast_sigmoid(float x) {
    return 1.f / (1.f + __expf(-x));
}
__device__ __forceinline__ float fast_tanh(float x) {
    float ax = fabsf(x);
    float e = __expf(-2.f * ax);
    float r = (1.f - e) / (1.f + e);
    return copysignf(r, x);
}

// ------------------------- init / prep -------------------------
__global__ void zero_state_kernel() {
    int idx = blockIdx.x * blockDim.x + threadIdx.x;
    if (idx < BPAD * HID / 2) ((uint32_t*)g_hz)[idx] = 0u;
    if (idx < 4) g_bar[idx] = 0u;
}

// x -> bf16, layout [t*512 + b][e]
__global__ void prep_xbf_kernel(const float* __restrict__ inp) {
    long long idx = (long long)blockIdx.x * blockDim.x + threadIdx.x;
    if (idx >= (long long)TSTEPS * BATCH * EMB) return;
    int e = (int)(idx & 511);
    long long r = idx >> 9;
    int b = (int)(r % BATCH);
    int t = (int)(r / BATCH);
    float v = inp[(size_t)b * TBSTRIDE + (size_t)t * EMB + e];
    g_xbf[((size_t)t * BPAD + b) * EMB + e] = __float2bfloat16_rn(v);
}

// zero the pad rows of g_xbf (b in [500,512)) so xg pad rows are finite
__global__ void zero_xbf_pad_kernel() {
    int idx = blockIdx.x * blockDim.x + threadIdx.x;
    int total = TSTEPS * 12 * EMB / 2;
    if (idx >= total) return;
    int per_t = 12 * EMB / 2;
    int t = idx / per_t;
    int o = idx - t * per_t;
    ((uint32_t*)(g_xbf + ((size_t)t * BPAD + BATCH) * EMB))[o] = 0u;
}

// permuted weights: row n' = j*4 + gate ; split Wih / Whh ; permuted bias
__global__ void prep_w_kernel(const float* __restrict__ Wih,
                              const float* __restrict__ Whh,
                              const float* __restrict__ bih,
                              const float* __restrict__ bhh) {
    int idx = blockIdx.x * blockDim.x + threadIdx.x;   // 0 .. 2M-1
    int np = idx >> 10;
    int k  = idx & 1023;
    int j = np >> 2, gate = np & 3;
    int n = gate * HID + j;
    if (k < 512) g_Wx[np * 512 + k] = __float2bfloat16_rn(Wih[(size_t)n * EMB + k]);
    else         g_Wh[np * 512 + (k - 512)] = __float2bfloat16_rn(Whh[(size_t)n * HID + (k - 512)]);
    if (idx < 2048) {
        int jj = idx >> 2, gg = idx & 3;
        g_pb[idx] = bih[gg * HID + jj] + bhh[gg * HID + jj];
    }
}

// ------------------------- bf16 mma helper -------------------------
__device__ __forceinline__ void mma_bf16(float* d, const uint32_t* a, const uint32_t* b) {
    asm volatile(
        "mma.sync.aligned.m16n8k16.row.col.f32.bf16.bf16.f32 "
        "{%0,%1,%2,%3}, {%4,%5,%6,%7}, {%8,%9}, {%0,%1,%2,%3};"
        : "+f"(d[0]), "+f"(d[1]), "+f"(d[2]), "+f"(d[3])
        : "r"(a[0]), "r"(a[1]), "r"(a[2]), "r"(a[3]), "r"(b[0]), "r"(b[1]));
}

// -------------------------------------------------------------------------
// Big parallel GEMM: g_xg[M=131072][2048] = g_xbf @ g_Wx^T (bf16 in, f32 out)
// -------------------------------------------------------------------------
#define XA_STRIDE 40
__global__ __launch_bounds__(256) void xg_gemm_kernel() {
    __shared__ __nv_bfloat16 As[2][128 * XA_STRIDE];
    __shared__ __nv_bfloat16 Bs[2][128 * XA_STRIDE];
    const int tid = threadIdx.x;
    const int lid = tid & 31, wid = tid >> 5;
    const int tg = lid & 3, gr = lid >> 2;
    const int mw = wid & 3, nw = wid >> 2;
    const size_t R0 = (size_t)blockIdx.x * 128;
    const int n0 = blockIdx.y * 128;

    float acc[2][8][4];
#pragma unroll
    for (int mf = 0; mf < 2; mf++)
#pragma unroll
        for (int nf = 0; nf < 8; nf++)
#pragma unroll
            for (int r = 0; r < 4; r++) acc[mf][nf][r] = 0.f;

    auto load_stage = [&](int s) {
        const int buf = s & 1;
        const int k0 = s * 32;
#pragma unroll
        for (int it = 0; it < 2; it++) {
            int idx = tid + 256 * it;
            int r = idx >> 2, ch = idx & 3;
            const __nv_bfloat16* src = g_xbf + (R0 + r) * EMB + k0 + ch * 8;
            uint32_t dst = (uint32_t)__cvta_generic_to_shared(&As[buf][r * XA_STRIDE + ch * 8]);
            asm volatile("cp.async.cg.shared.global [%0], [%1], 16;" :: "r"(dst), "l"(src));
        }
#pragma unroll
        for (int it = 0; it < 2; it++) {
            int idx = tid + 256 * it;
            int r = idx >> 2, ch = idx & 3;
            const __nv_bfloat16* src = g_Wx + (size_t)(n0 + r) * 512 + k0 + ch * 8;
            uint32_t dst = (uint32_t)__cvta_generic_to_shared(&Bs[buf][r * XA_STRIDE + ch * 8]);
            asm volatile("cp.async.cg.shared.global [%0], [%1], 16;" :: "r"(dst), "l"(src));
        }
        asm volatile("cp.async.commit_group;" ::: "memory");
    };

    load_stage(0);
#pragma unroll 1
    for (int s = 0; s < 16; s++) {
        if (s + 1 < 16) {
            load_stage(s + 1);
            asm volatile("cp.async.wait_group 1;" ::: "memory");
        } else {
            asm volatile("cp.async.wait_group 0;" ::: "memory");
        }
        __syncthreads();
        const int buf = s & 1;
        const __nv_bfloat16* Ab = &As[buf][(mw * 32) * XA_STRIDE];
        const __nv_bfloat16* Bb = &Bs[buf][(nw * 64) * XA_STRIDE];
#pragma unroll
        for (int ks = 0; ks < 2; ks++) {
            const int k = ks * 16 + tg * 2;
            uint32_t a[2][4];
#pragma unroll
            for (int mf = 0; mf < 2; mf++) {
                const __nv_bfloat16* p = Ab + (mf * 16 + gr) * XA_STRIDE + k;
                a[mf][0] = *(const uint32_t*)p;
                a[mf][1] = *(const uint32_t*)(p + 8 * XA_STRIDE);
                a[mf][2] = *(const uint32_t*)(p + 8);
                a[mf][3] = *(const uint32_t*)(p + 8 * XA_STRIDE + 8);
            }
#pragma unroll
            for (int nf = 0; nf < 8; nf++) {
                const __nv_bfloat16* p = Bb + (nf * 8 + gr) * XA_STRIDE + k;
                uint32_t b[2];
                b[0] = *(const uint32_t*)p;
                b[1] = *(const uint32_t*)(p + 8);
#pragma unroll
                for (int mf = 0; mf < 2; mf++) mma_bf16(acc[mf][nf], a[mf], b);
            }
        }
        __syncthreads();
    }

#pragma unroll
    for (int mf = 0; mf < 2; mf++)
#pragma unroll
        for (int nf = 0; nf < 8; nf++) {
            size_t R = R0 + mw * 32 + mf * 16 + gr;
            int c = n0 + nw * 64 + nf * 8 + 2 * tg;
            *(float2*)&g_xg[R * 2048 + c] = make_float2(acc[mf][nf][0], acc[mf][nf][1]);
            *(float2*)&g_xg[(R + 8) * 2048 + c] = make_float2(acc[mf][nf][2], acc[mf][nf][3]);
        }
}

// -------------------------------------------------------------------------
// Persistent LSTM kernel: 128 CTAs (4 m-groups x 32 n-tiles), 256 steps.
// h flows through t-indexed bf16 slabs (no aliasing). c in registers.
// -------------------------------------------------------------------------
#define WA_STRIDE 72          // A stage stride (bf16)
#define WB_STRIDE 520         // B smem stride (bf16)
#define XS_STRIDE 68          // xg stage stride (f32)
#define HS_STRIDE 17
#define OFF_B 0
#define OFF_A0 (64 * WB_STRIDE * 2)                    // 66560
#define OFF_A1 (OFF_A0 + 128 * WA_STRIDE * 2)
#define OFF_X  (OFF_A1 + 128 * WA_STRIDE * 2)
#define OFF_H  (OFF_X + 128 * XS_STRIDE * 4)
#define PERSIST_SMEM (OFF_H + 128 * HS_STRIDE * 4)     // 146944

__global__ __launch_bounds__(256) void lstm_persist_kernel() {
    extern __shared__ char sm[];
    __nv_bfloat16* Bs = (__nv_bfloat16*)(sm + OFF_B);
    float* Xs = (float*)(sm + OFF_X);
    float* Hs = (float*)(sm + OFF_H);

    const int tid = threadIdx.x;
    const int lid = tid & 31, wid = tid >> 5;
    const int tg = lid & 3, gr = lid >> 2;
    const int mw = wid & 3, nw = wid >> 2;
    const int mblk = blockIdx.x;
    const int m0 = mblk * 128;
    const int n0 = blockIdx.y * 64;
    const bool even = (tg & 1) == 0;

    // ---- load W_hh slice (64 rows x 512 bf16 = 4096 16B chunks) into smem once ----
#pragma unroll
    for (int it = 0; it < 16; it++) {
        int idx = tid + 256 * it;                     // 4096 chunks of 16B
        int r = idx >> 6, ch = idx & 63;              // 64 rows x 64 chunks (FIXED)
        const __nv_bfloat16* src = g_Wh + (size_t)(n0 + r) * 512 + ch * 8;
        uint32_t dst = (uint32_t)__cvta_generic_to_shared(&Bs[r * WB_STRIDE + ch * 8]);
        asm volatile("cp.async.cg.shared.global [%0], [%1], 16;" :: "r"(dst), "l"(src));
    }
    asm volatile("cp.async.commit_group;" ::: "memory");
    asm volatile("cp.async.wait_group 0;" ::: "memory");
    __syncthreads();

    float4 pb4[4];
#pragma unroll
    for (int nf = 0; nf < 4; nf++) {
        int jc = nw * 8 + 2 * nf + (tg >> 1);
        pb4[nf] = *(const float4*)&g_pb[n0 + jc * 4];
    }

    float creg[2][4][2];
#pragma unroll
    for (int mf = 0; mf < 2; mf++)
#pragma unroll
        for (int nf = 0; nf < 4; nf++) { creg[mf][nf][0] = 0.f; creg[mf][nf][1] = 0.f; }

#pragma unroll 1
    for (int t = 0; t < TSTEPS; t++) {
        // ---- fire xg slice load (independent of barrier) ----
#pragma unroll
        for (int it = 0; it < 8; it++) {
            int idx = tid + 256 * it;
            int r = idx >> 4, ch = idx & 15;
            const float* src = g_xg + ((size_t)t * BPAD + m0 + r) * 2048 + n0 + ch * 4;
            uint32_t dst = (uint32_t)__cvta_generic_to_shared(&Xs[r * XS_STRIDE + ch * 4]);
            asm volatile("cp.async.cg.shared.global [%0], [%1], 16;" :: "r"(dst), "l"(src));
        }
        asm volatile("cp.async.commit_group;" ::: "memory");

        // ---- wait: all 32 CTAs of this m-group finished step t-1 ----
        if (tid == 0 && t > 0) {
            unsigned target = 32u * (unsigned)t;
            unsigned v;
            do {
                asm volatile("ld.acquire.gpu.global.u32 %0, [%1];"
                             : "=r"(v) : "l"(&g_bar[mblk]) : "memory");
                if (v >= target) break;
                asm volatile("nanosleep.u32 128;");
            } while (true);
            __threadfence();
        }
        __syncthreads();

        const __nv_bfloat16* hsrc = (t == 0) ? g_hz
                                             : g_hb + (size_t)(t - 1) * BPAD * HID;

        auto load_stage = [&](int s) {
            char* Abuf = sm + ((s & 1) ? OFF_A1 : OFF_A0);
            const int k0 = s * 64;
#pragma unroll
            for (int it = 0; it < 4; it++) {
                int idx = tid + 256 * it;
                int r = idx >> 3, ch = idx & 7;
                const __nv_bfloat16* src = hsrc + (size_t)(m0 + r) * HID + k0 + ch * 8;
                uint32_t dst = (uint32_t)__cvta_generic_to_shared(
                    Abuf + (r * WA_STRIDE + ch * 8) * 2);
                asm volatile("cp.async.cg.shared.global [%0], [%1], 16;" :: "r"(dst), "l"(src));
            }
            asm volatile("cp.async.commit_group;" ::: "memory");
        };

        float acc[2][4][4];
#pragma unroll
        for (int mf = 0; mf < 2; mf++)
#pragma unroll
            for (int nf = 0; nf < 4; nf++)
#pragma unroll
                for (int r = 0; r < 4; r++) acc[mf][nf][r] = 0.f;

        load_stage(0);
#pragma unroll 1
        for (int s = 0; s < 8; s++) {
            if (s + 1 < 8) {
                load_stage(s + 1);
                asm volatile("cp.async.wait_group 1;" ::: "memory");
            } else {
                asm volatile("cp.async.wait_group 0;" ::: "memory");
            }
            __syncthreads();
            const __nv_bfloat16* Ab = (const __nv_bfloat16*)(sm + ((s & 1) ? OFF_A1 : OFF_A0))
                                      + (mw * 32) * WA_STRIDE;
            const __nv_bfloat16* Bb = Bs + (nw * 32) * WB_STRIDE + s * 64;
#pragma unroll
            for (int ks = 0; ks < 4; ks++) {
                const int k = ks * 16 + tg * 2;
                uint32_t a[2][4];
#pragma unroll
                for (int mf = 0; mf < 2; mf++) {
                    const __nv_bfloat16* p = Ab + (mf * 16 + gr) * WA_STRIDE + k;
                    a[mf][0] = *(const uint32_t*)p;
                    a[mf][1] = *(const uint32_t*)(p + 8 * WA_STRIDE);
                    a[mf][2] = *(const uint32_t*)(p + 8);
                    a[mf][3] = *(const uint32_t*)(p + 8 * WA_STRIDE + 8);
                }
#pragma unroll
                for (int nf = 0; nf < 4; nf++) {
                    const __nv_bfloat16* p = Bb + (nf * 8 + gr) * WB_STRIDE + k;
                    uint32_t b[2];
                    b[0] = *(const uint32_t*)p;
                    b[1] = *(const uint32_t*)(p + 8);
#pragma unroll
                    for (int mf = 0; mf < 2; mf++) mma_bf16(acc[mf][nf], a[mf], b);
                }
            }
            __syncthreads();
        }

        // ---- epilogue: + xg, + bias, gate exchange, cell update ----
#pragma unroll
        for (int mf = 0; mf < 2; mf++) {
            const int row = mw * 32 + mf * 16 + gr;
#pragma unroll
            for (int nf = 0; nf < 4; nf++) {
                const int cl = nw * 32 + nf * 8 + 2 * tg;
                float2 x0 = *(const float2*)&Xs[row * XS_STRIDE + cl];
                float2 x1 = *(const float2*)&Xs[(row + 8) * XS_STRIDE + cl];
                float b0 = even ? pb4[nf].x : pb4[nf].z;
                float b1 = even ? pb4[nf].y : pb4[nf].w;
                float v0 = acc[mf][nf][0] + x0.x + b0;
                float v1 = acc[mf][nf][1] + x0.y + b1;
                float v2 = acc[mf][nf][2] + x1.x + b0;
                float v3 = acc[mf][nf][3] + x1.y + b1;
                float s0 = __shfl_xor_sync(0xffffffffu, v0, 1);
                float s1 = __shfl_xor_sync(0xffffffffu, v1, 1);
                float s2 = __shfl_xor_sync(0xffffffffu, v2, 1);
                float s3 = __shfl_xor_sync(0xffffffffu, v3, 1);
                if (even) {
                    const int jc = nw * 8 + 2 * nf + (tg >> 1);
                    float ig0 = fast_sigmoid(v0), fg0 = fast_sigmoid(v1);
                    float gt0 = fast_tanh(s0),    ot0 = fast_sigmoid(s1);
                    float c0 = fg0 * creg[mf][nf][0] + ig0 * gt0;
                    creg[mf][nf][0] = c0;
                    Hs[row * HS_STRIDE + jc] = ot0 * fast_tanh(c0);
                    float ig1 = fast_sigmoid(v2), fg1 = fast_sigmoid(v3);
                    float gt1 = fast_tanh(s2),    ot1 = fast_sigmoid(s3);
                    float c1 = fg1 * creg[mf][nf][1] + ig1 * gt1;
                    creg[mf][nf][1] = c1;
                    Hs[(row + 8) * HS_STRIDE + jc] = ot1 * fast_tanh(c1);
                }
            }
        }
        __syncthreads();

        // ---- flush h: fp32 -> g_hall (b<BATCH), bf16 -> g_hb[t] (all rows) ----
        {
            const int row = tid >> 1, half = tid & 1;
            const int b = m0 + row;
            const int j0g = blockIdx.y * 16 + half * 8;
            float h[8];
            if (b < BATCH) {
#pragma unroll
                for (int i = 0; i < 8; i++) h[i] = Hs[row * HS_STRIDE + half * 8 + i];
                float* dst = g_hall + ((size_t)t * BATCH + b) * HID + j0g;
                *(float4*)&dst[0] = *(float4*)&h[0];
                *(float4*)&dst[4] = *(float4*)&h[4];
            } else {
#pragma unroll
                for (int i = 0; i < 8; i++) h[i] = 0.f;
            }
            unsigned short u[8];
#pragma unroll
            for (int i = 0; i < 8; i++) {
                __nv_bfloat16 bf = __float2bfloat16_rn(h[i]);
                u[i] = *(unsigned short*)&bf;
            }
            uint4 pk;
            pk.x = (uint32_t)u[0] | ((uint32_t)u[1] << 16);
            pk.y = (uint32_t)u[2] | ((uint32_t)u[3] << 16);
            pk.z = (uint32_t)u[4] | ((uint32_t)u[5] << 16);
            pk.w = (uint32_t)u[6] | ((uint32_t)u[7] << 16);
            *(uint4*)(g_hb + ((size_t)t * BPAD + b) * HID + j0g) = pk;
        }
        __threadfence();
        __syncthreads();
        if (tid == 0) atomicAdd(&g_bar[mblk], 1u);
    }
}

// -------------------------------------------------------------------------
// Final FC: out[b][t][o] = sigmoid(h_all[t][b] . W_fc[o] + b_fc[o])
// -------------------------------------------------------------------------
__global__ __launch_bounds__(256) void fc_gemm_kernel(
    const float* __restrict__ Wfc,
    const float* __restrict__ bfc,
    float* __restrict__ out)
{
    __shared__ float As[16][64];
    __shared__ float Ws[16][128];

    const int tid = threadIdx.x;
    const int tx = tid & 15;
    const int ty = tid >> 4;
    const int row0 = blockIdx.x * 64;

    const int arow = tid >> 2;
    const int ak   = (tid & 3) * 4;
    const int wn = tid >> 1;
    const int wk = (tid & 1) * 8;

    float acc[4][8];
#pragma unroll
    for (int i = 0; i < 4; i++)
#pragma unroll
        for (int j = 0; j < 8; j++) acc[i][j] = 0.f;

    for (int k0 = 0; k0 < 512; k0 += 16) {
        const float* Ap = g_hall + (size_t)(row0 + arow) * HID + k0 + ak;
        float4 av = *(const float4*)Ap;
        As[ak + 0][arow] = av.x;
        As[ak + 1][arow] = av.y;
        As[ak + 2][arow] = av.z;
        As[ak + 3][arow] = av.w;

        float4 w0 = make_float4(0.f, 0.f, 0.f, 0.f);
        float4 w1 = make_float4(0.f, 0.f, 0.f, 0.f);
        if (wn < NOUT) {
            const float* wrow = Wfc + (size_t)wn * 512 + k0 + wk;
            w0 = *(const float4*)(wrow);
            w1 = *(const float4*)(wrow + 4);
        }
        Ws[wk + 0][wn] = w0.x; Ws[wk + 1][wn] = w0.y;
        Ws[wk + 2][wn] = w0.z; Ws[wk + 3][wn] = w0.w;
        Ws[wk + 4][wn] = w1.x; Ws[wk + 5][wn] = w1.y;
        Ws[wk + 6][wn] = w1.z; Ws[wk + 7][wn] = w1.w;

        __syncthreads();

#pragma unroll
        for (int kk = 0; kk < 16; kk++) {
            float a[4], w[8];
            *(float4*)(a)     = *(const float4*)&As[kk][ty * 4];
            *(float4*)(w)     = *(const float4*)&Ws[kk][tx * 8];
            *(float4*)(w + 4) = *(const float4*)&Ws[kk][tx * 8 + 4];
#pragma unroll
            for (int i = 0; i < 4; i++)
#pragma unroll
                for (int j = 0; j < 8; j++) acc[i][j] += a[i] * w[j];
        }
        __syncthreads();
    }

    const int col = tx * 8;
#pragma unroll
    for (int i = 0; i < 4; i++) {
        int r = row0 + ty * 4 + i;      // r = t*BATCH + b
        int tt = r / BATCH;
        int bb = r - tt * BATCH;
        float* dst = out + ((size_t)bb * TSTEPS + tt) * NOUT;
#pragma unroll
        for (int j = 0; j < 8; j++) {
            int c = col + j;
            if (c < NOUT) dst[c] = fast_sigmoid(acc[i][j] + bfc[c]);
        }
    }
}

// -------------------------------------------------------------------------
extern "C" void kernel_launch(void* const* d_in, const int* in_sizes, int n_in,
                              void* d_out, int out_size) {
    const float* inp  = (const float*)d_in[0];
    const float* Wih  = (const float*)d_in[1];
    const float* Whh  = (const float*)d_in[2];
    const float* bih  = (const float*)d_in[3];
    const float* bhh  = (const float*)d_in[4];
    const float* Wfc  = (const float*)d_in[5];
    const float* bfc  = (const float*)d_in[6];
    float* out = (float*)d_out;

    cudaFuncSetAttribute(lstm_persist_kernel,
                         cudaFuncAttributeMaxDynamicSharedMemorySize, PERSIST_SMEM);

    zero_state_kernel<<<512, 256>>>();
    {
        long long total = (long long)TSTEPS * BATCH * EMB;
        int blocks = (int)((total + 255) / 256);
        prep_xbf_kernel<<<blocks, 256>>>(inp);
    }
    zero_xbf_pad_kernel<<<(TSTEPS * 12 * EMB / 2 + 255) / 256, 256>>>();
    prep_w_kernel<<<(2048 * 1024) / 256, 256>>>(Wih, Whh, bih, bhh);

    xg_gemm_kernel<<<dim3(MROWS / 128, 16), 256>>>();

    lstm_persist_kernel<<<dim3(4, 32), 256, PERSIST_SMEM>>>();

    fc_gemm_kernel<<<2000, 256>>>(Wfc, bfc, out);
}

// round 7
// speedup vs baseline: 6.9876x; 1.1572x over previous
#include <cuda_runtime.h>
#include <cuda_bf16.h>
#include <math.h>
#include <stdint.h>

#define BATCH 500
#define BPAD 512
#define TSTEPS 256
#define EMB 512
#define HID 512
#define NOUT 100
#define TBSTRIDE (TSTEPS * EMB)
#define MROWS (TSTEPS * BPAD)        // 131072

// ------------------------- device globals (scratch) -------------------------
__device__ __nv_bfloat16 g_xbf[(size_t)MROWS * EMB];        // 134MB  [t*512+b][e]
__device__ __nv_bfloat16 g_Wx[2048 * 512];                  // permuted Wih bf16
__device__ __nv_bfloat16 g_Wh[2048 * 512];                  // permuted Whh bf16
__device__ __nv_bfloat16 g_Wf[128 * 512];                   // Wfc bf16, padded to 128 rows
__device__ float g_pb[2048];                                // permuted bias
__device__ __nv_bfloat16 g_xg[(size_t)MROWS * 2048];        // 540MB xg bf16
__device__ __nv_bfloat16 g_hb[(size_t)TSTEPS * BPAD * HID]; // 134MB bf16 h, t-indexed
__device__ __nv_bfloat16 g_hz[BPAD * HID];                  // zero h slab for t=0
__device__ unsigned g_bar[4];                               // per-m-group counters

__device__ __forceinline__ float fast_sigmoid(float x) {
    return 1.f / (1.f + __expf(-x));
}
__device__ __forceinline__ float fast_tanh(float x) {
    float ax = fabsf(x);
    float e = __expf(-2.f * ax);
    float r = (1.f - e) / (1.f + e);
    return copysignf(r, x);
}

// ------------------------- init / prep -------------------------
__global__ void zero_state_kernel() {
    int idx = blockIdx.x * blockDim.x + threadIdx.x;
    if (idx < BPAD * HID / 2) ((uint32_t*)g_hz)[idx] = 0u;
    if (idx < 4) g_bar[idx] = 0u;
}

__global__ void prep_xbf_kernel(const float* __restrict__ inp) {
    long long idx = (long long)blockIdx.x * blockDim.x + threadIdx.x;
    if (idx >= (long long)TSTEPS * BATCH * EMB) return;
    int e = (int)(idx & 511);
    long long r = idx >> 9;
    int b = (int)(r % BATCH);
    int t = (int)(r / BATCH);
    float v = inp[(size_t)b * TBSTRIDE + (size_t)t * EMB + e];
    g_xbf[((size_t)t * BPAD + b) * EMB + e] = __float2bfloat16_rn(v);
}

__global__ void zero_xbf_pad_kernel() {
    int idx = blockIdx.x * blockDim.x + threadIdx.x;
    int total = TSTEPS * 12 * EMB / 2;
    if (idx >= total) return;
    int per_t = 12 * EMB / 2;
    int t = idx / per_t;
    int o = idx - t * per_t;
    ((uint32_t*)(g_xbf + ((size_t)t * BPAD + BATCH) * EMB))[o] = 0u;
}

// permuted weights: row n' = j*4 + gate ; split Wih / Whh ; bias ; Wfc pad
__global__ void prep_w_kernel(const float* __restrict__ Wih,
                              const float* __restrict__ Whh,
                              const float* __restrict__ bih,
                              const float* __restrict__ bhh,
                              const float* __restrict__ Wfc) {
    int idx = blockIdx.x * blockDim.x + threadIdx.x;   // 0 .. 2M-1
    int np = idx >> 10;
    int k  = idx & 1023;
    int j = np >> 2, gate = np & 3;
    int n = gate * HID + j;
    if (k < 512) g_Wx[np * 512 + k] = __float2bfloat16_rn(Wih[(size_t)n * EMB + k]);
    else         g_Wh[np * 512 + (k - 512)] = __float2bfloat16_rn(Whh[(size_t)n * HID + (k - 512)]);
    if (idx < 2048) {
        int jj = idx >> 2, gg = idx & 3;
        g_pb[idx] = bih[gg * HID + jj] + bhh[gg * HID + jj];
    }
    if (idx < 128 * 512) {
        int fn = idx >> 9, fk = idx & 511;
        g_Wf[idx] = (fn < NOUT) ? __float2bfloat16_rn(Wfc[(size_t)fn * 512 + fk])
                                : __float2bfloat16_rn(0.f);
    }
}

// ------------------------- bf16 mma helper -------------------------
__device__ __forceinline__ void mma_bf16(float* d, const uint32_t* a, const uint32_t* b) {
    asm volatile(
        "mma.sync.aligned.m16n8k16.row.col.f32.bf16.bf16.f32 "
        "{%0,%1,%2,%3}, {%4,%5,%6,%7}, {%8,%9}, {%0,%1,%2,%3};"
        : "+f"(d[0]), "+f"(d[1]), "+f"(d[2]), "+f"(d[3])
        : "r"(a[0]), "r"(a[1]), "r"(a[2]), "r"(a[3]), "r"(b[0]), "r"(b[1]));
}

// -------------------------------------------------------------------------
// Big parallel GEMM: g_xg[131072][2048](bf16) = g_xbf @ g_Wx^T
// -------------------------------------------------------------------------
#define XA_STRIDE 40
__global__ __launch_bounds__(256) void xg_gemm_kernel() {
    __shared__ __nv_bfloat16 As[2][128 * XA_STRIDE];
    __shared__ __nv_bfloat16 Bs[2][128 * XA_STRIDE];
    const int tid = threadIdx.x;
    const int lid = tid & 31, wid = tid >> 5;
    const int tg = lid & 3, gr = lid >> 2;
    const int mw = wid & 3, nw = wid >> 2;
    const size_t R0 = (size_t)blockIdx.x * 128;
    const int n0 = blockIdx.y * 128;

    float acc[2][8][4];
#pragma unroll
    for (int mf = 0; mf < 2; mf++)
#pragma unroll
        for (int nf = 0; nf < 8; nf++)
#pragma unroll
            for (int r = 0; r < 4; r++) acc[mf][nf][r] = 0.f;

    auto load_stage = [&](int s) {
        const int buf = s & 1;
        const int k0 = s * 32;
#pragma unroll
        for (int it = 0; it < 2; it++) {
            int idx = tid + 256 * it;
            int r = idx >> 2, ch = idx & 3;
            const __nv_bfloat16* src = g_xbf + (R0 + r) * EMB + k0 + ch * 8;
            uint32_t dst = (uint32_t)__cvta_generic_to_shared(&As[buf][r * XA_STRIDE + ch * 8]);
            asm volatile("cp.async.cg.shared.global [%0], [%1], 16;" :: "r"(dst), "l"(src));
        }
#pragma unroll
        for (int it = 0; it < 2; it++) {
            int idx = tid + 256 * it;
            int r = idx >> 2, ch = idx & 3;
            const __nv_bfloat16* src = g_Wx + (size_t)(n0 + r) * 512 + k0 + ch * 8;
            uint32_t dst = (uint32_t)__cvta_generic_to_shared(&Bs[buf][r * XA_STRIDE + ch * 8]);
            asm volatile("cp.async.cg.shared.global [%0], [%1], 16;" :: "r"(dst), "l"(src));
        }
        asm volatile("cp.async.commit_group;" ::: "memory");
    };

    load_stage(0);
#pragma unroll 1
    for (int s = 0; s < 16; s++) {
        if (s + 1 < 16) {
            load_stage(s + 1);
            asm volatile("cp.async.wait_group 1;" ::: "memory");
        } else {
            asm volatile("cp.async.wait_group 0;" ::: "memory");
        }
        __syncthreads();
        const int buf = s & 1;
        const __nv_bfloat16* Ab = &As[buf][(mw * 32) * XA_STRIDE];
        const __nv_bfloat16* Bb = &Bs[buf][(nw * 64) * XA_STRIDE];
#pragma unroll
        for (int ks = 0; ks < 2; ks++) {
            const int k = ks * 16 + tg * 2;
            uint32_t a[2][4];
#pragma unroll
            for (int mf = 0; mf < 2; mf++) {
                const __nv_bfloat16* p = Ab + (mf * 16 + gr) * XA_STRIDE + k;
                a[mf][0] = *(const uint32_t*)p;
                a[mf][1] = *(const uint32_t*)(p + 8 * XA_STRIDE);
                a[mf][2] = *(const uint32_t*)(p + 8);
                a[mf][3] = *(const uint32_t*)(p + 8 * XA_STRIDE + 8);
            }
#pragma unroll
            for (int nf = 0; nf < 8; nf++) {
                const __nv_bfloat16* p = Bb + (nf * 8 + gr) * XA_STRIDE + k;
                uint32_t b[2];
                b[0] = *(const uint32_t*)p;
                b[1] = *(const uint32_t*)(p + 8);
#pragma unroll
                for (int mf = 0; mf < 2; mf++) mma_bf16(acc[mf][nf], a[mf], b);
            }
        }
        __syncthreads();
    }

    uint32_t* xg32 = (uint32_t*)g_xg;   // 1024 u32 per row
#pragma unroll
    for (int mf = 0; mf < 2; mf++)
#pragma unroll
        for (int nf = 0; nf < 8; nf++) {
            size_t R = R0 + mw * 32 + mf * 16 + gr;
            int c = n0 + nw * 64 + nf * 8 + 2 * tg;   // even
            __nv_bfloat162 lo = __float22bfloat162_rn(make_float2(acc[mf][nf][0], acc[mf][nf][1]));
            __nv_bfloat162 hi = __float22bfloat162_rn(make_float2(acc[mf][nf][2], acc[mf][nf][3]));
            xg32[R * 1024 + (c >> 1)]       = *(uint32_t*)&lo;
            xg32[(R + 8) * 1024 + (c >> 1)] = *(uint32_t*)&hi;
        }
}

// -------------------------------------------------------------------------
// Persistent LSTM: 128 CTAs (4 m-groups x 32 n-tiles), 256 steps.
// Full h A-tile (128x512 bf16) loaded per step in ONE cp.async burst.
// W_hh slice resident in smem. c in registers. xg prefetched to regs.
// -------------------------------------------------------------------------
#define ST 520                                  // smem row stride (bf16)
#define HS_STRIDE 17
#define OFF_B 0
#define OFF_A (64 * ST * 2)                     // 66560
#define OFF_H (OFF_A + 128 * ST * 2)            // 199680
#define PERSIST_SMEM (OFF_H + 128 * HS_STRIDE * 4)   // 208384

__global__ __launch_bounds__(256) void lstm_persist_kernel() {
    extern __shared__ char sm[];
    __nv_bfloat16* Bs = (__nv_bfloat16*)(sm + OFF_B);
    __nv_bfloat16* As = (__nv_bfloat16*)(sm + OFF_A);
    float* Hs = (float*)(sm + OFF_H);

    const int tid = threadIdx.x;
    const int lid = tid & 31, wid = tid >> 5;
    const int tg = lid & 3, gr = lid >> 2;
    const int mw = wid & 3, nw = wid >> 2;
    const int mblk = blockIdx.x;
    const int m0 = mblk * 128;
    const int n0 = blockIdx.y * 64;
    const bool even = (tg & 1) == 0;

    // ---- W_hh slice (64 rows x 512 bf16) into smem once ----
#pragma unroll
    for (int it = 0; it < 16; it++) {
        int idx = tid + 256 * it;                 // 4096 chunks of 16B
        int r = idx >> 6, ch = idx & 63;
        const __nv_bfloat16* src = g_Wh + (size_t)(n0 + r) * 512 + ch * 8;
        uint32_t dst = (uint32_t)__cvta_generic_to_shared(&Bs[r * ST + ch * 8]);
        asm volatile("cp.async.cg.shared.global [%0], [%1], 16;" :: "r"(dst), "l"(src));
    }
    asm volatile("cp.async.commit_group;" ::: "memory");
    asm volatile("cp.async.wait_group 0;" ::: "memory");
    __syncthreads();

    float4 pb4[4];
#pragma unroll
    for (int nf = 0; nf < 4; nf++) {
        int jc = nw * 8 + 2 * nf + (tg >> 1);
        pb4[nf] = *(const float4*)&g_pb[n0 + jc * 4];
    }

    float creg[2][4][2];
#pragma unroll
    for (int mf = 0; mf < 2; mf++)
#pragma unroll
        for (int nf = 0; nf < 4; nf++) { creg[mf][nf][0] = 0.f; creg[mf][nf][1] = 0.f; }

    const uint32_t* xg32 = (const uint32_t*)g_xg;
    const int colu = (n0 + nw * 32 + 2 * tg) >> 1;   // u32 col base (nf adds 4 each)

#pragma unroll 1
    for (int t = 0; t < TSTEPS; t++) {
        // ---- prefetch xg epilogue values (independent of barrier) ----
        uint32_t xr[2][4][2];
        {
            const size_t rb = (size_t)t * BPAD + m0 + mw * 32 + gr;
#pragma unroll
            for (int mf = 0; mf < 2; mf++)
#pragma unroll
                for (int nf = 0; nf < 4; nf++) {
                    const size_t r0 = (rb + mf * 16) * 1024 + colu + nf * 4;
                    xr[mf][nf][0] = __ldg(xg32 + r0);
                    xr[mf][nf][1] = __ldg(xg32 + r0 + 8 * 1024);
                }
        }

        // ---- wait: all 32 CTAs of this m-group finished step t-1 ----
        if (tid == 0 && t > 0) {
            const unsigned target = 32u * (unsigned)t;
            unsigned v;
            do {
                asm volatile("ld.acquire.gpu.global.u32 %0, [%1];"
                             : "=r"(v) : "l"(&g_bar[mblk]) : "memory");
            } while (v < target);
        }
        __syncthreads();

        // ---- load FULL h A-tile (128 x 512 bf16) in one burst ----
        const __nv_bfloat16* hsrc = (t == 0) ? g_hz
                                             : g_hb + (size_t)(t - 1) * BPAD * HID;
#pragma unroll
        for (int it = 0; it < 32; it++) {
            int idx = tid + 256 * it;             // 8192 chunks of 16B
            int r = idx >> 6, ch = idx & 63;
            const __nv_bfloat16* src = hsrc + (size_t)(m0 + r) * HID + ch * 8;
            uint32_t dst = (uint32_t)__cvta_generic_to_shared(&As[r * ST + ch * 8]);
            asm volatile("cp.async.cg.shared.global [%0], [%1], 16;" :: "r"(dst), "l"(src));
        }
        asm volatile("cp.async.commit_group;" ::: "memory");
        asm volatile("cp.async.wait_group 0;" ::: "memory");
        __syncthreads();

        // ---- MMA over full K=512, no intermediate syncs ----
        float acc[2][4][4];
#pragma unroll
        for (int mf = 0; mf < 2; mf++)
#pragma unroll
            for (int nf = 0; nf < 4; nf++)
#pragma unroll
                for (int r = 0; r < 4; r++) acc[mf][nf][r] = 0.f;

        const __nv_bfloat16* Ab = As + (mw * 32) * ST;
        const __nv_bfloat16* Bb = Bs + (nw * 32) * ST;
#pragma unroll 8
        for (int kk = 0; kk < 32; kk++) {
            const int k = kk * 16 + tg * 2;
            uint32_t a[2][4];
#pragma unroll
            for (int mf = 0; mf < 2; mf++) {
                const __nv_bfloat16* p = Ab + (mf * 16 + gr) * ST + k;
                a[mf][0] = *(const uint32_t*)p;
                a[mf][1] = *(const uint32_t*)(p + 8 * ST);
                a[mf][2] = *(const uint32_t*)(p + 8);
                a[mf][3] = *(const uint32_t*)(p + 8 * ST + 8);
            }
#pragma unroll
            for (int nf = 0; nf < 4; nf++) {
                const __nv_bfloat16* p = Bb + (nf * 8 + gr) * ST + k;
                uint32_t b[2];
                b[0] = *(const uint32_t*)p;
                b[1] = *(const uint32_t*)(p + 8);
#pragma unroll
                for (int mf = 0; mf < 2; mf++) mma_bf16(acc[mf][nf], a[mf], b);
            }
        }

        // ---- epilogue: + xg, + bias, gate exchange, cell update ----
#pragma unroll
        for (int mf = 0; mf < 2; mf++) {
            const int row = mw * 32 + mf * 16 + gr;
#pragma unroll
            for (int nf = 0; nf < 4; nf++) {
                float2 x0 = __bfloat1622float2(*(__nv_bfloat162*)&xr[mf][nf][0]);
                float2 x1 = __bfloat1622float2(*(__nv_bfloat162*)&xr[mf][nf][1]);
                float b0 = even ? pb4[nf].x : pb4[nf].z;
                float b1 = even ? pb4[nf].y : pb4[nf].w;
                float v0 = acc[mf][nf][0] + x0.x + b0;
                float v1 = acc[mf][nf][1] + x0.y + b1;
                float v2 = acc[mf][nf][2] + x1.x + b0;
                float v3 = acc[mf][nf][3] + x1.y + b1;
                float s0 = __shfl_xor_sync(0xffffffffu, v0, 1);
                float s1 = __shfl_xor_sync(0xffffffffu, v1, 1);
                float s2 = __shfl_xor_sync(0xffffffffu, v2, 1);
                float s3 = __shfl_xor_sync(0xffffffffu, v3, 1);
                if (even) {
                    const int jc = nw * 8 + 2 * nf + (tg >> 1);
                    float ig0 = fast_sigmoid(v0), fg0 = fast_sigmoid(v1);
                    float gt0 = fast_tanh(s0),    ot0 = fast_sigmoid(s1);
                    float c0 = fg0 * creg[mf][nf][0] + ig0 * gt0;
                    creg[mf][nf][0] = c0;
                    Hs[row * HS_STRIDE + jc] = ot0 * fast_tanh(c0);
                    float ig1 = fast_sigmoid(v2), fg1 = fast_sigmoid(v3);
                    float gt1 = fast_tanh(s2),    ot1 = fast_sigmoid(s3);
                    float c1 = fg1 * creg[mf][nf][1] + ig1 * gt1;
                    creg[mf][nf][1] = c1;
                    Hs[(row + 8) * HS_STRIDE + jc] = ot1 * fast_tanh(c1);
                }
            }
        }
        __syncthreads();

        // ---- flush h -> g_hb[t] (bf16; pad rows zero) ----
        {
            const int row = tid >> 1, half = tid & 1;
            const int b = m0 + row;
            const int j0g = blockIdx.y * 16 + half * 8;
            float h[8];
            if (b < BATCH) {
#pragma unroll
                for (int i = 0; i < 8; i++) h[i] = Hs[row * HS_STRIDE + half * 8 + i];
            } else {
#pragma unroll
                for (int i = 0; i < 8; i++) h[i] = 0.f;
            }
            unsigned short u[8];
#pragma unroll
            for (int i = 0; i < 8; i++) {
                __nv_bfloat16 bf = __float2bfloat16_rn(h[i]);
                u[i] = *(unsigned short*)&bf;
            }
            uint4 pk;
            pk.x = (uint32_t)u[0] | ((uint32_t)u[1] << 16);
            pk.y = (uint32_t)u[2] | ((uint32_t)u[3] << 16);
            pk.z = (uint32_t)u[4] | ((uint32_t)u[5] << 16);
            pk.w = (uint32_t)u[6] | ((uint32_t)u[7] << 16);
            *(uint4*)(g_hb + ((size_t)t * BPAD + b) * HID + j0g) = pk;
        }
        __threadfence();
        __syncthreads();
        if (tid == 0) atomicAdd(&g_bar[mblk], 1u);
    }
}

// -------------------------------------------------------------------------
// FC (bf16 mma): out[b][t][o] = sigmoid(g_hb[t][b] . W_fc[o] + b_fc[o])
// M = 131072 (t*512+b rows), N = 128 (100 real), K = 512
// -------------------------------------------------------------------------
__global__ __launch_bounds__(256) void fc_gemm_kernel(
    const float* __restrict__ bfc,
    float* __restrict__ out)
{
    __shared__ __nv_bfloat16 As[2][128 * XA_STRIDE];
    __shared__ __nv_bfloat16 Bs[2][128 * XA_STRIDE];
    const int tid = threadIdx.x;
    const int lid = tid & 31, wid = tid >> 5;
    const int tg = lid & 3, gr = lid >> 2;
    const int mw = wid & 3, nw = wid >> 2;
    const size_t R0 = (size_t)blockIdx.x * 128;

    float acc[2][8][4];
#pragma unroll
    for (int mf = 0; mf < 2; mf++)
#pragma unroll
        for (int nf = 0; nf < 8; nf++)
#pragma unroll
            for (int r = 0; r < 4; r++) acc[mf][nf][r] = 0.f;

    auto load_stage = [&](int s) {
        const int buf = s & 1;
        const int k0 = s * 32;
#pragma unroll
        for (int it = 0; it < 2; it++) {
            int idx = tid + 256 * it;
            int r = idx >> 2, ch = idx & 3;
            const __nv_bfloat16* src = g_hb + (R0 + r) * HID + k0 + ch * 8;
            uint32_t dst = (uint32_t)__cvta_generic_to_shared(&As[buf][r * XA_STRIDE + ch * 8]);
            asm volatile("cp.async.cg.shared.global [%0], [%1], 16;" :: "r"(dst), "l"(src));
        }
#pragma unroll
        for (int it = 0; it < 2; it++) {
            int idx = tid + 256 * it;
            int r = idx >> 2, ch = idx & 3;
            const __nv_bfloat16* src = g_Wf + (size_t)r * 512 + k0 + ch * 8;
            uint32_t dst = (uint32_t)__cvta_generic_to_shared(&Bs[buf][r * XA_STRIDE + ch * 8]);
            asm volatile("cp.async.cg.shared.global [%0], [%1], 16;" :: "r"(dst), "l"(src));
        }
        asm volatile("cp.async.commit_group;" ::: "memory");
    };

    load_stage(0);
#pragma unroll 1
    for (int s = 0; s < 16; s++) {
        if (s + 1 < 16) {
            load_stage(s + 1);
            asm volatile("cp.async.wait_group 1;" ::: "memory");
        } else {
            asm volatile("cp.async.wait_group 0;" ::: "memory");
        }
        __syncthreads();
        const int buf = s & 1;
        const __nv_bfloat16* Ab = &As[buf][(mw * 32) * XA_STRIDE];
        const __nv_bfloat16* Bb = &Bs[buf][(nw * 64) * XA_STRIDE];
#pragma unroll
        for (int ks = 0; ks < 2; ks++) {
            const int k = ks * 16 + tg * 2;
            uint32_t a[2][4];
#pragma unroll
            for (int mf = 0; mf < 2; mf++) {
                const __nv_bfloat16* p = Ab + (mf * 16 + gr) * XA_STRIDE + k;
                a[mf][0] = *(const uint32_t*)p;
                a[mf][1] = *(const uint32_t*)(p + 8 * XA_STRIDE);
                a[mf][2] = *(const uint32_t*)(p + 8);
                a[mf][3] = *(const uint32_t*)(p + 8 * XA_STRIDE + 8);
            }
#pragma unroll
            for (int nf = 0; nf < 8; nf++) {
                const __nv_bfloat16* p = Bb + (nf * 8 + gr) * XA_STRIDE + k;
                uint32_t b[2];
                b[0] = *(const uint32_t*)p;
                b[1] = *(const uint32_t*)(p + 8);
#pragma unroll
                for (int mf = 0; mf < 2; mf++) mma_bf16(acc[mf][nf], a[mf], b);
            }
        }
        __syncthreads();
    }

#pragma unroll
    for (int mf = 0; mf < 2; mf++)
#pragma unroll
        for (int nf = 0; nf < 8; nf++) {
            const int c = nw * 64 + nf * 8 + 2 * tg;
            if (c >= NOUT) continue;
#pragma unroll
            for (int half = 0; half < 2; half++) {
                size_t R = R0 + mw * 32 + mf * 16 + gr + half * 8;
                int t = (int)(R >> 9);
                int b = (int)(R & 511);
                if (b < BATCH) {
                    float* dst = out + ((size_t)b * TSTEPS + t) * NOUT + c;
                    dst[0] = fast_sigmoid(acc[mf][nf][half * 2 + 0] + bfc[c]);
                    dst[1] = fast_sigmoid(acc[mf][nf][half * 2 + 1] + bfc[c + 1]);
                }
            }
        }
}

// -------------------------------------------------------------------------
extern "C" void kernel_launch(void* const* d_in, const int* in_sizes, int n_in,
                              void* d_out, int out_size) {
    const float* inp  = (const float*)d_in[0];
    const float* Wih  = (const float*)d_in[1];
    const float* Whh  = (const float*)d_in[2];
    const float* bih  = (const float*)d_in[3];
    const float* bhh  = (const float*)d_in[4];
    const float* Wfc  = (const float*)d_in[5];
    const float* bfc  = (const float*)d_in[6];
    float* out = (float*)d_out;

    cudaFuncSetAttribute(lstm_persist_kernel,
                         cudaFuncAttributeMaxDynamicSharedMemorySize, PERSIST_SMEM);

    zero_state_kernel<<<512, 256>>>();
    {
        long long total = (long long)TSTEPS * BATCH * EMB;
        int blocks = (int)((total + 255) / 256);
        prep_xbf_kernel<<<blocks, 256>>>(inp);
    }
    zero_xbf_pad_kernel<<<(TSTEPS * 12 * EMB / 2 + 255) / 256, 256>>>();
    prep_w_kernel<<<(2048 * 1024) / 256, 256>>>(Wih, Whh, bih, bhh, Wfc);

    xg_gemm_kernel<<<dim3(MROWS / 128, 16), 256>>>();

    lstm_persist_kernel<<<dim3(4, 32), 256, PERSIST_SMEM>>>();

    fc_gemm_kernel<<<1024, 256>>>(bfc, out);
}

// round 8
// speedup vs baseline: 7.6432x; 1.0938x over previous
#include <cuda_runtime.h>
#include <cuda_bf16.h>
#include <math.h>
#include <stdint.h>

#define BATCH 500
#define BPAD 512
#define TSTEPS 256
#define EMB 512
#define HID 512
#define NOUT 100
#define TBSTRIDE (TSTEPS * EMB)
#define MROWS (TSTEPS * BPAD)        // 131072

// ------------------------- device globals (scratch) -------------------------
__device__ __nv_bfloat16 g_xbf[(size_t)MROWS * EMB];        // 134MB  [t*512+b][e]
__device__ __nv_bfloat16 g_Wx[2048 * 512];                  // permuted Wih bf16
__device__ __nv_bfloat16 g_Wh[2048 * 512];                  // permuted Whh bf16
__device__ __nv_bfloat16 g_Wf[128 * 512];                   // Wfc bf16, padded
__device__ float g_pb[2048];                                // permuted bias
__device__ __nv_bfloat16 g_xg[(size_t)MROWS * 2048];        // 540MB xg bf16
__device__ __nv_bfloat16 g_hb[(size_t)TSTEPS * BPAD * HID]; // 134MB bf16 h, t-indexed
__device__ __nv_bfloat16 g_hz[BPAD * HID];                  // zero h slab for t=0
__device__ unsigned g_bar[4];                               // per-m-group counters

__device__ __forceinline__ float fast_sigmoid(float x) {
    return 1.f / (1.f + __expf(-x));
}
__device__ __forceinline__ float fast_tanh(float x) {
    float ax = fabsf(x);
    float e = __expf(-2.f * ax);
    float r = (1.f - e) / (1.f + e);
    return copysignf(r, x);
}

// ------------------------- init / prep -------------------------
__global__ void zero_state_kernel() {
    int idx = blockIdx.x * blockDim.x + threadIdx.x;
    if (idx < BPAD * HID / 2) ((uint32_t*)g_hz)[idx] = 0u;
    if (idx < 4) g_bar[idx] = 0u;
}

__global__ void prep_xbf_kernel(const float* __restrict__ inp) {
    long long idx = (long long)blockIdx.x * blockDim.x + threadIdx.x;
    if (idx >= (long long)TSTEPS * BATCH * EMB) return;
    int e = (int)(idx & 511);
    long long r = idx >> 9;
    int b = (int)(r % BATCH);
    int t = (int)(r / BATCH);
    float v = inp[(size_t)b * TBSTRIDE + (size_t)t * EMB + e];
    g_xbf[((size_t)t * BPAD + b) * EMB + e] = __float2bfloat16_rn(v);
}

__global__ void zero_xbf_pad_kernel() {
    int idx = blockIdx.x * blockDim.x + threadIdx.x;
    int total = TSTEPS * 12 * EMB / 2;
    if (idx >= total) return;
    int per_t = 12 * EMB / 2;
    int t = idx / per_t;
    int o = idx - t * per_t;
    ((uint32_t*)(g_xbf + ((size_t)t * BPAD + BATCH) * EMB))[o] = 0u;
}

__global__ void prep_w_kernel(const float* __restrict__ Wih,
                              const float* __restrict__ Whh,
                              const float* __restrict__ bih,
                              const float* __restrict__ bhh,
                              const float* __restrict__ Wfc) {
    int idx = blockIdx.x * blockDim.x + threadIdx.x;
    int np = idx >> 10;
    int k  = idx & 1023;
    int j = np >> 2, gate = np & 3;
    int n = gate * HID + j;
    if (k < 512) g_Wx[np * 512 + k] = __float2bfloat16_rn(Wih[(size_t)n * EMB + k]);
    else         g_Wh[np * 512 + (k - 512)] = __float2bfloat16_rn(Whh[(size_t)n * HID + (k - 512)]);
    if (idx < 2048) {
        int jj = idx >> 2, gg = idx & 3;
        g_pb[idx] = bih[gg * HID + jj] + bhh[gg * HID + jj];
    }
    if (idx < 128 * 512) {
        int fn = idx >> 9, fk = idx & 511;
        g_Wf[idx] = (fn < NOUT) ? __float2bfloat16_rn(Wfc[(size_t)fn * 512 + fk])
                                : __float2bfloat16_rn(0.f);
    }
}

// ------------------------- mma / ldmatrix helpers -------------------------
__device__ __forceinline__ void mma_bf16(float* d, const uint32_t* a, const uint32_t* b) {
    asm volatile(
        "mma.sync.aligned.m16n8k16.row.col.f32.bf16.bf16.f32 "
        "{%0,%1,%2,%3}, {%4,%5,%6,%7}, {%8,%9}, {%0,%1,%2,%3};"
        : "+f"(d[0]), "+f"(d[1]), "+f"(d[2]), "+f"(d[3])
        : "r"(a[0]), "r"(a[1]), "r"(a[2]), "r"(a[3]), "r"(b[0]), "r"(b[1]));
}
__device__ __forceinline__ void ldsm_x4(uint32_t* r, uint32_t addr) {
    asm volatile("ldmatrix.sync.aligned.m8n8.x4.shared.b16 {%0,%1,%2,%3}, [%4];"
                 : "=r"(r[0]), "=r"(r[1]), "=r"(r[2]), "=r"(r[3]) : "r"(addr));
}

// -------------------------------------------------------------------------
// Big parallel GEMM: g_xg[131072][2048](bf16) = g_xbf @ g_Wx^T  (unchanged)
// -------------------------------------------------------------------------
#define XA_STRIDE 40
__global__ __launch_bounds__(256) void xg_gemm_kernel() {
    __shared__ __nv_bfloat16 As[2][128 * XA_STRIDE];
    __shared__ __nv_bfloat16 Bs[2][128 * XA_STRIDE];
    const int tid = threadIdx.x;
    const int lid = tid & 31, wid = tid >> 5;
    const int tg = lid & 3, gr = lid >> 2;
    const int mw = wid & 3, nw = wid >> 2;
    const size_t R0 = (size_t)blockIdx.x * 128;
    const int n0 = blockIdx.y * 128;

    float acc[2][8][4];
#pragma unroll
    for (int mf = 0; mf < 2; mf++)
#pragma unroll
        for (int nf = 0; nf < 8; nf++)
#pragma unroll
            for (int r = 0; r < 4; r++) acc[mf][nf][r] = 0.f;

    auto load_stage = [&](int s) {
        const int buf = s & 1;
        const int k0 = s * 32;
#pragma unroll
        for (int it = 0; it < 2; it++) {
            int idx = tid + 256 * it;
            int r = idx >> 2, ch = idx & 3;
            const __nv_bfloat16* src = g_xbf + (R0 + r) * EMB + k0 + ch * 8;
            uint32_t dst = (uint32_t)__cvta_generic_to_shared(&As[buf][r * XA_STRIDE + ch * 8]);
            asm volatile("cp.async.cg.shared.global [%0], [%1], 16;" :: "r"(dst), "l"(src));
        }
#pragma unroll
        for (int it = 0; it < 2; it++) {
            int idx = tid + 256 * it;
            int r = idx >> 2, ch = idx & 3;
            const __nv_bfloat16* src = g_Wx + (size_t)(n0 + r) * 512 + k0 + ch * 8;
            uint32_t dst = (uint32_t)__cvta_generic_to_shared(&Bs[buf][r * XA_STRIDE + ch * 8]);
            asm volatile("cp.async.cg.shared.global [%0], [%1], 16;" :: "r"(dst), "l"(src));
        }
        asm volatile("cp.async.commit_group;" ::: "memory");
    };

    load_stage(0);
#pragma unroll 1
    for (int s = 0; s < 16; s++) {
        if (s + 1 < 16) {
            load_stage(s + 1);
            asm volatile("cp.async.wait_group 1;" ::: "memory");
        } else {
            asm volatile("cp.async.wait_group 0;" ::: "memory");
        }
        __syncthreads();
        const int buf = s & 1;
        const __nv_bfloat16* Ab = &As[buf][(mw * 32) * XA_STRIDE];
        const __nv_bfloat16* Bb = &Bs[buf][(nw * 64) * XA_STRIDE];
#pragma unroll
        for (int ks = 0; ks < 2; ks++) {
            const int k = ks * 16 + tg * 2;
            uint32_t a[2][4];
#pragma unroll
            for (int mf = 0; mf < 2; mf++) {
                const __nv_bfloat16* p = Ab + (mf * 16 + gr) * XA_STRIDE + k;
                a[mf][0] = *(const uint32_t*)p;
                a[mf][1] = *(const uint32_t*)(p + 8 * XA_STRIDE);
                a[mf][2] = *(const uint32_t*)(p + 8);
                a[mf][3] = *(const uint32_t*)(p + 8 * XA_STRIDE + 8);
            }
#pragma unroll
            for (int nf = 0; nf < 8; nf++) {
                const __nv_bfloat16* p = Bb + (nf * 8 + gr) * XA_STRIDE + k;
                uint32_t b[2];
                b[0] = *(const uint32_t*)p;
                b[1] = *(const uint32_t*)(p + 8);
#pragma unroll
                for (int mf = 0; mf < 2; mf++) mma_bf16(acc[mf][nf], a[mf], b);
            }
        }
        __syncthreads();
    }

    uint32_t* xg32 = (uint32_t*)g_xg;
#pragma unroll
    for (int mf = 0; mf < 2; mf++)
#pragma unroll
        for (int nf = 0; nf < 8; nf++) {
            size_t R = R0 + mw * 32 + mf * 16 + gr;
            int c = n0 + nw * 64 + nf * 8 + 2 * tg;
            __nv_bfloat162 lo = __float22bfloat162_rn(make_float2(acc[mf][nf][0], acc[mf][nf][1]));
            __nv_bfloat162 hi = __float22bfloat162_rn(make_float2(acc[mf][nf][2], acc[mf][nf][3]));
            xg32[R * 1024 + (c >> 1)]       = *(uint32_t*)&lo;
            xg32[(R + 8) * 1024 + (c >> 1)] = *(uint32_t*)&hi;
        }
}

// -------------------------------------------------------------------------
// Persistent LSTM: 128 CTAs (4 m-groups x 32 n-tiles), 256 steps.
// ldmatrix fragments, split-K pipelined A-tile load, direct global h stores.
// -------------------------------------------------------------------------
#define ST 520                                  // smem row stride (bf16)
#define OFF_B 0
#define OFF_A (64 * ST * 2)                     // 66560
#define PERSIST_SMEM (OFF_A + 128 * ST * 2)     // 199680

__global__ __launch_bounds__(256) void lstm_persist_kernel() {
    extern __shared__ char sm[];
    __nv_bfloat16* Bs = (__nv_bfloat16*)(sm + OFF_B);
    __nv_bfloat16* As = (__nv_bfloat16*)(sm + OFF_A);

    const int tid = threadIdx.x;
    const int lid = tid & 31, wid = tid >> 5;
    const int tg = lid & 3, gr = lid >> 2;
    const int mw = wid & 3, nw = wid >> 2;
    const int mblk = blockIdx.x;
    const int m0 = mblk * 128;
    const int n0 = blockIdx.y * 64;
    const bool even = (tg & 1) == 0;

    // ---- W_hh slice (64 rows x 512 bf16) into smem once ----
#pragma unroll
    for (int it = 0; it < 16; it++) {
        int idx = tid + 256 * it;
        int r = idx >> 6, ch = idx & 63;
        const __nv_bfloat16* src = g_Wh + (size_t)(n0 + r) * 512 + ch * 8;
        uint32_t dst = (uint32_t)__cvta_generic_to_shared(&Bs[r * ST + ch * 8]);
        asm volatile("cp.async.cg.shared.global [%0], [%1], 16;" :: "r"(dst), "l"(src));
    }
    asm volatile("cp.async.commit_group;" ::: "memory");
    asm volatile("cp.async.wait_group 0;" ::: "memory");
    __syncthreads();

    // ---- ldmatrix base addresses (constant across steps) ----
    uint32_t aaddr[2], baddr[2];
    {
        const uint32_t abase = (uint32_t)__cvta_generic_to_shared(As);
        const uint32_t bbase = (uint32_t)__cvta_generic_to_shared(Bs);
        const int arow = mw * 32 + (lid & 15);
        const int acol = (lid >> 4) << 3;
#pragma unroll
        for (int mf = 0; mf < 2; mf++)
            aaddr[mf] = abase + (uint32_t)((arow + mf * 16) * ST + acol) * 2;
        const int brow_base = nw * 32 + ((lid >> 4) << 3) + (lid & 7);
        const int bcol = ((lid >> 3) & 1) << 3;
#pragma unroll
        for (int p = 0; p < 2; p++)
            baddr[p] = bbase + (uint32_t)((brow_base + p * 16) * ST + bcol) * 2;
    }

    float4 pb4[4];
#pragma unroll
    for (int nf = 0; nf < 4; nf++) {
        int jc = nw * 8 + 2 * nf + (tg >> 1);
        pb4[nf] = *(const float4*)&g_pb[n0 + jc * 4];
    }

    float creg[2][4][2];
#pragma unroll
    for (int mf = 0; mf < 2; mf++)
#pragma unroll
        for (int nf = 0; nf < 4; nf++) { creg[mf][nf][0] = 0.f; creg[mf][nf][1] = 0.f; }

    const uint32_t* xg32 = (const uint32_t*)g_xg;
    const int colu = (n0 + nw * 32 + 2 * tg) >> 1;

#pragma unroll 1
    for (int t = 0; t < TSTEPS; t++) {
        // ---- prefetch xg epilogue values (independent of barrier) ----
        uint32_t xr[2][4][2];
        {
            const size_t rb = (size_t)t * BPAD + m0 + mw * 32 + gr;
#pragma unroll
            for (int mf = 0; mf < 2; mf++)
#pragma unroll
                for (int nf = 0; nf < 4; nf++) {
                    const size_t r0 = (rb + mf * 16) * 1024 + colu + nf * 4;
                    xr[mf][nf][0] = __ldg(xg32 + r0);
                    xr[mf][nf][1] = __ldg(xg32 + r0 + 8 * 1024);
                }
        }

        // ---- wait: all 32 CTAs of this m-group finished step t-1 ----
        if (tid == 0 && t > 0) {
            const unsigned target = 32u * (unsigned)t;
            unsigned v;
            do {
                asm volatile("ld.acquire.gpu.global.u32 %0, [%1];"
                             : "=r"(v) : "l"(&g_bar[mblk]) : "memory");
            } while (v < target);
        }
        __syncthreads();

        // ---- issue BOTH K-halves of the h A-tile as separate groups ----
        const __nv_bfloat16* hsrc = (t == 0) ? g_hz
                                             : g_hb + (size_t)(t - 1) * BPAD * HID;
#pragma unroll
        for (int it = 0; it < 16; it++) {          // half 0: k [0,256)
            int idx = tid + 256 * it;
            int r = idx >> 5, ch = idx & 31;
            const __nv_bfloat16* src = hsrc + (size_t)(m0 + r) * HID + ch * 8;
            uint32_t dst = (uint32_t)__cvta_generic_to_shared(&As[r * ST + ch * 8]);
            asm volatile("cp.async.cg.shared.global [%0], [%1], 16;" :: "r"(dst), "l"(src));
        }
        asm volatile("cp.async.commit_group;" ::: "memory");
#pragma unroll
        for (int it = 0; it < 16; it++) {          // half 1: k [256,512)
            int idx = tid + 256 * it;
            int r = idx >> 5, ch = (idx & 31) + 32;
            const __nv_bfloat16* src = hsrc + (size_t)(m0 + r) * HID + ch * 8;
            uint32_t dst = (uint32_t)__cvta_generic_to_shared(&As[r * ST + ch * 8]);
            asm volatile("cp.async.cg.shared.global [%0], [%1], 16;" :: "r"(dst), "l"(src));
        }
        asm volatile("cp.async.commit_group;" ::: "memory");

        float acc[2][4][4];
#pragma unroll
        for (int mf = 0; mf < 2; mf++)
#pragma unroll
            for (int nf = 0; nf < 4; nf++)
#pragma unroll
                for (int r = 0; r < 4; r++) acc[mf][nf][r] = 0.f;

        // ---- half 0 compute (half 1 load in flight) ----
        asm volatile("cp.async.wait_group 1;" ::: "memory");
        __syncthreads();
#pragma unroll
        for (int kk = 0; kk < 16; kk++) {
            uint32_t a0[4], a1[4], b01[4], b23[4];
            ldsm_x4(a0, aaddr[0] + kk * 32);
            ldsm_x4(a1, aaddr[1] + kk * 32);
            ldsm_x4(b01, baddr[0] + kk * 32);
            ldsm_x4(b23, baddr[1] + kk * 32);
            mma_bf16(acc[0][0], a0, b01);     mma_bf16(acc[0][1], a0, b01 + 2);
            mma_bf16(acc[0][2], a0, b23);     mma_bf16(acc[0][3], a0, b23 + 2);
            mma_bf16(acc[1][0], a1, b01);     mma_bf16(acc[1][1], a1, b01 + 2);
            mma_bf16(acc[1][2], a1, b23);     mma_bf16(acc[1][3], a1, b23 + 2);
        }
        // ---- half 1 compute ----
        asm volatile("cp.async.wait_group 0;" ::: "memory");
        __syncthreads();
#pragma unroll
        for (int kk = 16; kk < 32; kk++) {
            uint32_t a0[4], a1[4], b01[4], b23[4];
            ldsm_x4(a0, aaddr[0] + kk * 32);
            ldsm_x4(a1, aaddr[1] + kk * 32);
            ldsm_x4(b01, baddr[0] + kk * 32);
            ldsm_x4(b23, baddr[1] + kk * 32);
            mma_bf16(acc[0][0], a0, b01);     mma_bf16(acc[0][1], a0, b01 + 2);
            mma_bf16(acc[0][2], a0, b23);     mma_bf16(acc[0][3], a0, b23 + 2);
            mma_bf16(acc[1][0], a1, b01);     mma_bf16(acc[1][1], a1, b01 + 2);
            mma_bf16(acc[1][2], a1, b23);     mma_bf16(acc[1][3], a1, b23 + 2);
        }

        // ---- epilogue: + xg, + bias, gate exchange, cell update, direct h store ----
        __nv_bfloat16* hb = g_hb + (size_t)t * BPAD * HID;
#pragma unroll
        for (int mf = 0; mf < 2; mf++) {
            const int row = mw * 32 + mf * 16 + gr;
#pragma unroll
            for (int nf = 0; nf < 4; nf++) {
                float2 x0 = __bfloat1622float2(*(__nv_bfloat162*)&xr[mf][nf][0]);
                float2 x1 = __bfloat1622float2(*(__nv_bfloat162*)&xr[mf][nf][1]);
                float b0 = even ? pb4[nf].x : pb4[nf].z;
                float b1 = even ? pb4[nf].y : pb4[nf].w;
                float v0 = acc[mf][nf][0] + x0.x + b0;
                float v1 = acc[mf][nf][1] + x0.y + b1;
                float v2 = acc[mf][nf][2] + x1.x + b0;
                float v3 = acc[mf][nf][3] + x1.y + b1;
                float s0 = __shfl_xor_sync(0xffffffffu, v0, 1);
                float s1 = __shfl_xor_sync(0xffffffffu, v1, 1);
                float s2 = __shfl_xor_sync(0xffffffffu, v2, 1);
                float s3 = __shfl_xor_sync(0xffffffffu, v3, 1);
                if (even) {
                    const int jg = blockIdx.y * 16 + nw * 8 + 2 * nf + (tg >> 1);
                    float ig0 = fast_sigmoid(v0), fg0 = fast_sigmoid(v1);
                    float gt0 = fast_tanh(s0),    ot0 = fast_sigmoid(s1);
                    float c0 = fg0 * creg[mf][nf][0] + ig0 * gt0;
                    creg[mf][nf][0] = c0;
                    hb[(size_t)(m0 + row) * HID + jg] =
                        __float2bfloat16_rn(ot0 * fast_tanh(c0));
                    float ig1 = fast_sigmoid(v2), fg1 = fast_sigmoid(v3);
                    float gt1 = fast_tanh(s2),    ot1 = fast_sigmoid(s3);
                    float c1 = fg1 * creg[mf][nf][1] + ig1 * gt1;
                    creg[mf][nf][1] = c1;
                    hb[(size_t)(m0 + row + 8) * HID + jg] =
                        __float2bfloat16_rn(ot1 * fast_tanh(c1));
                }
            }
        }
        __threadfence();
        __syncthreads();
        if (tid == 0) atomicAdd(&g_bar[mblk], 1u);
    }
}

// -------------------------------------------------------------------------
// FC (bf16 mma): out[b][t][o] = sigmoid(g_hb[t][b] . W_fc[o] + b_fc[o])
// -------------------------------------------------------------------------
__global__ __launch_bounds__(256) void fc_gemm_kernel(
    const float* __restrict__ bfc,
    float* __restrict__ out)
{
    __shared__ __nv_bfloat16 As[2][128 * XA_STRIDE];
    __shared__ __nv_bfloat16 Bs[2][128 * XA_STRIDE];
    const int tid = threadIdx.x;
    const int lid = tid & 31, wid = tid >> 5;
    const int tg = lid & 3, gr = lid >> 2;
    const int mw = wid & 3, nw = wid >> 2;
    const size_t R0 = (size_t)blockIdx.x * 128;

    float acc[2][8][4];
#pragma unroll
    for (int mf = 0; mf < 2; mf++)
#pragma unroll
        for (int nf = 0; nf < 8; nf++)
#pragma unroll
            for (int r = 0; r < 4; r++) acc[mf][nf][r] = 0.f;

    auto load_stage = [&](int s) {
        const int buf = s & 1;
        const int k0 = s * 32;
#pragma unroll
        for (int it = 0; it < 2; it++) {
            int idx = tid + 256 * it;
            int r = idx >> 2, ch = idx & 3;
            const __nv_bfloat16* src = g_hb + (R0 + r) * HID + k0 + ch * 8;
            uint32_t dst = (uint32_t)__cvta_generic_to_shared(&As[buf][r * XA_STRIDE + ch * 8]);
            asm volatile("cp.async.cg.shared.global [%0], [%1], 16;" :: "r"(dst), "l"(src));
        }
#pragma unroll
        for (int it = 0; it < 2; it++) {
            int idx = tid + 256 * it;
            int r = idx >> 2, ch = idx & 3;
            const __nv_bfloat16* src = g_Wf + (size_t)r * 512 + k0 + ch * 8;
            uint32_t dst = (uint32_t)__cvta_generic_to_shared(&Bs[buf][r * XA_STRIDE + ch * 8]);
            asm volatile("cp.async.cg.shared.global [%0], [%1], 16;" :: "r"(dst), "l"(src));
        }
        asm volatile("cp.async.commit_group;" ::: "memory");
    };

    load_stage(0);
#pragma unroll 1
    for (int s = 0; s < 16; s++) {
        if (s + 1 < 16) {
            load_stage(s + 1);
            asm volatile("cp.async.wait_group 1;" ::: "memory");
        } else {
            asm volatile("cp.async.wait_group 0;" ::: "memory");
        }
        __syncthreads();
        const int buf = s & 1;
        const __nv_bfloat16* Ab = &As[buf][(mw * 32) * XA_STRIDE];
        const __nv_bfloat16* Bb = &Bs[buf][(nw * 64) * XA_STRIDE];
#pragma unroll
        for (int ks = 0; ks < 2; ks++) {
            const int k = ks * 16 + tg * 2;
            uint32_t a[2][4];
#pragma unroll
            for (int mf = 0; mf < 2; mf++) {
                const __nv_bfloat16* p = Ab + (mf * 16 + gr) * XA_STRIDE + k;
                a[mf][0] = *(const uint32_t*)p;
                a[mf][1] = *(const uint32_t*)(p + 8 * XA_STRIDE);
                a[mf][2] = *(const uint32_t*)(p + 8);
                a[mf][3] = *(const uint32_t*)(p + 8 * XA_STRIDE + 8);
            }
#pragma unroll
            for (int nf = 0; nf < 8; nf++) {
                const __nv_bfloat16* p = Bb + (nf * 8 + gr) * XA_STRIDE + k;
                uint32_t b[2];
                b[0] = *(const uint32_t*)p;
                b[1] = *(const uint32_t*)(p + 8);
#pragma unroll
                for (int mf = 0; mf < 2; mf++) mma_bf16(acc[mf][nf], a[mf], b);
            }
        }
        __syncthreads();
    }

#pragma unroll
    for (int mf = 0; mf < 2; mf++)
#pragma unroll
        for (int nf = 0; nf < 8; nf++) {
            const int c = nw * 64 + nf * 8 + 2 * tg;
            if (c >= NOUT) continue;
#pragma unroll
            for (int half = 0; half < 2; half++) {
                size_t R = R0 + mw * 32 + mf * 16 + gr + half * 8;
                int t = (int)(R >> 9);
                int b = (int)(R & 511);
                if (b < BATCH) {
                    float* dst = out + ((size_t)b * TSTEPS + t) * NOUT + c;
                    dst[0] = fast_sigmoid(acc[mf][nf][half * 2 + 0] + bfc[c]);
                    dst[1] = fast_sigmoid(acc[mf][nf][half * 2 + 1] + bfc[c + 1]);
                }
            }
        }
}

// -------------------------------------------------------------------------
extern "C" void kernel_launch(void* const* d_in, const int* in_sizes, int n_in,
                              void* d_out, int out_size) {
    const float* inp  = (const float*)d_in[0];
    const float* Wih  = (const float*)d_in[1];
    const float* Whh  = (const float*)d_in[2];
    const float* bih  = (const float*)d_in[3];
    const float* bhh  = (const float*)d_in[4];
    const float* Wfc  = (const float*)d_in[5];
    const float* bfc  = (const float*)d_in[6];
    float* out = (float*)d_out;

    cudaFuncSetAttribute(lstm_persist_kernel,
                         cudaFuncAttributeMaxDynamicSharedMemorySize, PERSIST_SMEM);

    zero_state_kernel<<<512, 256>>>();
    {
        long long total = (long long)TSTEPS * BATCH * EMB;
        int blocks = (int)((total + 255) / 256);
        prep_xbf_kernel<<<blocks, 256>>>(inp);
    }
    zero_xbf_pad_kernel<<<(TSTEPS * 12 * EMB / 2 + 255) / 256, 256>>>();
    prep_w_kernel<<<(2048 * 1024) / 256, 256>>>(Wih, Whh, bih, bhh, Wfc);

    xg_gemm_kernel<<<dim3(MROWS / 128, 16), 256>>>();

    lstm_persist_kernel<<<dim3(4, 32), 256, PERSIST_SMEM>>>();

    fc_gemm_kernel<<<1024, 256>>>(bfc, out);
}

// round 9
// speedup vs baseline: 7.9250x; 1.0369x over previous
#include <cuda_runtime.h>
#include <cuda_bf16.h>
#include <math.h>
#include <stdint.h>

#define BATCH 500
#define BPAD 512
#define TSTEPS 256
#define EMB 512
#define HID 512
#define NOUT 100
#define TBSTRIDE (TSTEPS * EMB)
#define MROWS (TSTEPS * BPAD)        // 131072

// ------------------------- device globals (scratch) -------------------------
__device__ __nv_bfloat16 g_xbf[(size_t)MROWS * EMB];        // 134MB  [t*512+b][e]
__device__ __nv_bfloat16 g_Wx[2048 * 512];                  // permuted Wih bf16
__device__ __nv_bfloat16 g_Wh[2048 * 512];                  // permuted Whh bf16
__device__ __nv_bfloat16 g_Wf[128 * 512];                   // Wfc bf16, padded
__device__ float g_pb[2048];                                // permuted bias
__device__ __nv_bfloat16 g_xg[(size_t)MROWS * 2048];        // 540MB xg bf16
__device__ __nv_bfloat16 g_hb[(size_t)TSTEPS * BPAD * HID]; // 134MB bf16 h, t-indexed
__device__ __nv_bfloat16 g_hz[BPAD * HID];                  // zero h slab for t=0
__device__ unsigned g_bar[4];                               // per-m-group counters

__device__ __forceinline__ float fast_sigmoid(float x) {
    return 1.f / (1.f + __expf(-x));
}
__device__ __forceinline__ float fast_tanh(float x) {
    float ax = fabsf(x);
    float e = __expf(-2.f * ax);
    float r = (1.f - e) / (1.f + e);
    return copysignf(r, x);
}

// ------------------------- init / prep -------------------------
__global__ void zero_state_kernel() {
    int idx = blockIdx.x * blockDim.x + threadIdx.x;
    if (idx < BPAD * HID / 2) ((uint32_t*)g_hz)[idx] = 0u;
    if (idx < 4) g_bar[idx] = 0u;
}

__global__ void prep_xbf_kernel(const float* __restrict__ inp) {
    long long idx = (long long)blockIdx.x * blockDim.x + threadIdx.x;
    if (idx >= (long long)TSTEPS * BATCH * EMB) return;
    int e = (int)(idx & 511);
    long long r = idx >> 9;
    int b = (int)(r % BATCH);
    int t = (int)(r / BATCH);
    float v = inp[(size_t)b * TBSTRIDE + (size_t)t * EMB + e];
    g_xbf[((size_t)t * BPAD + b) * EMB + e] = __float2bfloat16_rn(v);
}

__global__ void zero_xbf_pad_kernel() {
    int idx = blockIdx.x * blockDim.x + threadIdx.x;
    int total = TSTEPS * 12 * EMB / 2;
    if (idx >= total) return;
    int per_t = 12 * EMB / 2;
    int t = idx / per_t;
    int o = idx - t * per_t;
    ((uint32_t*)(g_xbf + ((size_t)t * BPAD + BATCH) * EMB))[o] = 0u;
}

__global__ void prep_w_kernel(const float* __restrict__ Wih,
                              const float* __restrict__ Whh,
                              const float* __restrict__ bih,
                              const float* __restrict__ bhh,
                              const float* __restrict__ Wfc) {
    int idx = blockIdx.x * blockDim.x + threadIdx.x;
    int np = idx >> 10;
    int k  = idx & 1023;
    int j = np >> 2, gate = np & 3;
    int n = gate * HID + j;
    if (k < 512) g_Wx[np * 512 + k] = __float2bfloat16_rn(Wih[(size_t)n * EMB + k]);
    else         g_Wh[np * 512 + (k - 512)] = __float2bfloat16_rn(Whh[(size_t)n * HID + (k - 512)]);
    if (idx < 2048) {
        int jj = idx >> 2, gg = idx & 3;
        g_pb[idx] = bih[gg * HID + jj] + bhh[gg * HID + jj];
    }
    if (idx < 128 * 512) {
        int fn = idx >> 9, fk = idx & 511;
        g_Wf[idx] = (fn < NOUT) ? __float2bfloat16_rn(Wfc[(size_t)fn * 512 + fk])
                                : __float2bfloat16_rn(0.f);
    }
}

// ------------------------- mma / ldmatrix helpers -------------------------
__device__ __forceinline__ void mma_bf16(float* d, const uint32_t* a, const uint32_t* b) {
    asm volatile(
        "mma.sync.aligned.m16n8k16.row.col.f32.bf16.bf16.f32 "
        "{%0,%1,%2,%3}, {%4,%5,%6,%7}, {%8,%9}, {%0,%1,%2,%3};"
        : "+f"(d[0]), "+f"(d[1]), "+f"(d[2]), "+f"(d[3])
        : "r"(a[0]), "r"(a[1]), "r"(a[2]), "r"(a[3]), "r"(b[0]), "r"(b[1]));
}
__device__ __forceinline__ void ldsm_x4(uint32_t* r, uint32_t addr) {
    asm volatile("ldmatrix.sync.aligned.m8n8.x4.shared.b16 {%0,%1,%2,%3}, [%4];"
                 : "=r"(r[0]), "=r"(r[1]), "=r"(r[2]), "=r"(r[3]) : "r"(addr));
}

// -------------------------------------------------------------------------
// Big parallel GEMM: g_xg[131072][2048](bf16) = g_xbf @ g_Wx^T
// ldmatrix fragments, BK=64, double-buffered. Dynamic smem 73728 B.
// -------------------------------------------------------------------------
#define XS2 72
#define XBUF (128 * XS2)             // bf16 per buffer per matrix
#define XG_SMEM (4 * XBUF * 2)       // 73728 bytes

__global__ __launch_bounds__(256) void xg_gemm_kernel() {
    extern __shared__ __nv_bfloat16 xsm[];
    __nv_bfloat16* As = xsm;                 // [2][XBUF]
    __nv_bfloat16* Bs = xsm + 2 * XBUF;      // [2][XBUF]
    const int tid = threadIdx.x;
    const int lid = tid & 31, wid = tid >> 5;
    const int tg = lid & 3, gr = lid >> 2;
    const int mw = wid & 3, nw = wid >> 2;
    const size_t R0 = (size_t)blockIdx.x * 128;
    const int n0 = blockIdx.y * 128;

    float acc[2][8][4];
#pragma unroll
    for (int mf = 0; mf < 2; mf++)
#pragma unroll
        for (int nf = 0; nf < 8; nf++)
#pragma unroll
            for (int r = 0; r < 4; r++) acc[mf][nf][r] = 0.f;

    // ldmatrix addresses per buffer
    uint32_t aA[2][2], bB[2][4];
    {
        const uint32_t abase = (uint32_t)__cvta_generic_to_shared(As);
        const uint32_t bbase = (uint32_t)__cvta_generic_to_shared(Bs);
        const int arow = mw * 32 + (lid & 15);
        const int acol = (lid >> 4) << 3;
        const int brb = nw * 64 + ((lid >> 4) << 3) + (lid & 7);
        const int bcol = ((lid >> 3) & 1) << 3;
#pragma unroll
        for (int buf = 0; buf < 2; buf++) {
#pragma unroll
            for (int mf = 0; mf < 2; mf++)
                aA[buf][mf] = abase + (uint32_t)(buf * XBUF + (arow + mf * 16) * XS2 + acol) * 2;
#pragma unroll
            for (int p = 0; p < 4; p++)
                bB[buf][p] = bbase + (uint32_t)(buf * XBUF + (brb + p * 16) * XS2 + bcol) * 2;
        }
    }

    auto load_stage = [&](int s) {
        const int buf = s & 1;
        const int k0 = s * 64;
#pragma unroll
        for (int it = 0; it < 4; it++) {
            int idx = tid + 256 * it;
            int r = idx >> 3, ch = idx & 7;
            const __nv_bfloat16* src = g_xbf + (R0 + r) * EMB + k0 + ch * 8;
            uint32_t dst = (uint32_t)__cvta_generic_to_shared(&As[buf * XBUF + r * XS2 + ch * 8]);
            asm volatile("cp.async.cg.shared.global [%0], [%1], 16;" :: "r"(dst), "l"(src));
        }
#pragma unroll
        for (int it = 0; it < 4; it++) {
            int idx = tid + 256 * it;
            int r = idx >> 3, ch = idx & 7;
            const __nv_bfloat16* src = g_Wx + (size_t)(n0 + r) * 512 + k0 + ch * 8;
            uint32_t dst = (uint32_t)__cvta_generic_to_shared(&Bs[buf * XBUF + r * XS2 + ch * 8]);
            asm volatile("cp.async.cg.shared.global [%0], [%1], 16;" :: "r"(dst), "l"(src));
        }
        asm volatile("cp.async.commit_group;" ::: "memory");
    };

    load_stage(0);
#pragma unroll 1
    for (int s = 0; s < 8; s++) {
        if (s + 1 < 8) {
            load_stage(s + 1);
            asm volatile("cp.async.wait_group 1;" ::: "memory");
        } else {
            asm volatile("cp.async.wait_group 0;" ::: "memory");
        }
        __syncthreads();
        const int buf = s & 1;
#pragma unroll
        for (int kk = 0; kk < 4; kk++) {
            uint32_t a0[4], a1[4];
            ldsm_x4(a0, aA[buf][0] + kk * 32);
            ldsm_x4(a1, aA[buf][1] + kk * 32);
#pragma unroll
            for (int p = 0; p < 4; p++) {
                uint32_t bb[4];
                ldsm_x4(bb, bB[buf][p] + kk * 32);
                mma_bf16(acc[0][2 * p],     a0, bb);
                mma_bf16(acc[0][2 * p + 1], a0, bb + 2);
                mma_bf16(acc[1][2 * p],     a1, bb);
                mma_bf16(acc[1][2 * p + 1], a1, bb + 2);
            }
        }
        __syncthreads();
    }

    uint32_t* xg32 = (uint32_t*)g_xg;
#pragma unroll
    for (int mf = 0; mf < 2; mf++)
#pragma unroll
        for (int nf = 0; nf < 8; nf++) {
            size_t R = R0 + mw * 32 + mf * 16 + gr;
            int c = n0 + nw * 64 + nf * 8 + 2 * tg;
            __nv_bfloat162 lo = __float22bfloat162_rn(make_float2(acc[mf][nf][0], acc[mf][nf][1]));
            __nv_bfloat162 hi = __float22bfloat162_rn(make_float2(acc[mf][nf][2], acc[mf][nf][3]));
            xg32[R * 1024 + (c >> 1)]       = *(uint32_t*)&lo;
            xg32[(R + 8) * 1024 + (c >> 1)] = *(uint32_t*)&hi;
        }
}

// -------------------------------------------------------------------------
// Persistent LSTM: 128 CTAs (4 m-groups x 32 n-tiles), 256 steps.
// ldmatrix fragments, split-K pipelined A-tile load, coalesced h flush.
// -------------------------------------------------------------------------
#define ST 520                                  // smem row stride (bf16)
#define HS2 24                                  // h staging stride (bf16)
#define OFF_B 0
#define OFF_A (64 * ST * 2)                     // 66560
#define OFF_HS (OFF_A + 128 * ST * 2)           // 199680
#define PERSIST_SMEM (OFF_HS + 128 * HS2 * 2)   // 205824

__global__ __launch_bounds__(256) void lstm_persist_kernel() {
    extern __shared__ char sm[];
    __nv_bfloat16* Bs = (__nv_bfloat16*)(sm + OFF_B);
    __nv_bfloat16* As = (__nv_bfloat16*)(sm + OFF_A);
    __nv_bfloat16* Hsb = (__nv_bfloat16*)(sm + OFF_HS);

    const int tid = threadIdx.x;
    const int lid = tid & 31, wid = tid >> 5;
    const int tg = lid & 3, gr = lid >> 2;
    const int mw = wid & 3, nw = wid >> 2;
    const int mblk = blockIdx.x;
    const int m0 = mblk * 128;
    const int n0 = blockIdx.y * 64;
    const bool even = (tg & 1) == 0;

    // ---- W_hh slice (64 rows x 512 bf16) into smem once ----
#pragma unroll
    for (int it = 0; it < 16; it++) {
        int idx = tid + 256 * it;
        int r = idx >> 6, ch = idx & 63;
        const __nv_bfloat16* src = g_Wh + (size_t)(n0 + r) * 512 + ch * 8;
        uint32_t dst = (uint32_t)__cvta_generic_to_shared(&Bs[r * ST + ch * 8]);
        asm volatile("cp.async.cg.shared.global [%0], [%1], 16;" :: "r"(dst), "l"(src));
    }
    asm volatile("cp.async.commit_group;" ::: "memory");
    asm volatile("cp.async.wait_group 0;" ::: "memory");
    __syncthreads();

    // ---- ldmatrix base addresses ----
    uint32_t aaddr[2], baddr[2];
    {
        const uint32_t abase = (uint32_t)__cvta_generic_to_shared(As);
        const uint32_t bbase = (uint32_t)__cvta_generic_to_shared(Bs);
        const int arow = mw * 32 + (lid & 15);
        const int acol = (lid >> 4) << 3;
#pragma unroll
        for (int mf = 0; mf < 2; mf++)
            aaddr[mf] = abase + (uint32_t)((arow + mf * 16) * ST + acol) * 2;
        const int brow_base = nw * 32 + ((lid >> 4) << 3) + (lid & 7);
        const int bcol = ((lid >> 3) & 1) << 3;
#pragma unroll
        for (int p = 0; p < 2; p++)
            baddr[p] = bbase + (uint32_t)((brow_base + p * 16) * ST + bcol) * 2;
    }

    float4 pb4[4];
#pragma unroll
    for (int nf = 0; nf < 4; nf++) {
        int jc = nw * 8 + 2 * nf + (tg >> 1);
        pb4[nf] = *(const float4*)&g_pb[n0 + jc * 4];
    }

    float creg[2][4][2];
#pragma unroll
    for (int mf = 0; mf < 2; mf++)
#pragma unroll
        for (int nf = 0; nf < 4; nf++) { creg[mf][nf][0] = 0.f; creg[mf][nf][1] = 0.f; }

    const uint32_t* xg32 = (const uint32_t*)g_xg;
    const int colu = (n0 + nw * 32 + 2 * tg) >> 1;

#pragma unroll 1
    for (int t = 0; t < TSTEPS; t++) {
        // ---- prefetch xg epilogue values (independent of barrier) ----
        uint32_t xr[2][4][2];
        {
            const size_t rb = (size_t)t * BPAD + m0 + mw * 32 + gr;
#pragma unroll
            for (int mf = 0; mf < 2; mf++)
#pragma unroll
                for (int nf = 0; nf < 4; nf++) {
                    const size_t r0 = (rb + mf * 16) * 1024 + colu + nf * 4;
                    xr[mf][nf][0] = __ldg(xg32 + r0);
                    xr[mf][nf][1] = __ldg(xg32 + r0 + 8 * 1024);
                }
        }

        // ---- wait: all 32 CTAs of this m-group finished step t-1 ----
        if (tid == 0 && t > 0) {
            const unsigned target = 32u * (unsigned)t;
            unsigned v;
            do {
                asm volatile("ld.acquire.gpu.global.u32 %0, [%1];"
                             : "=r"(v) : "l"(&g_bar[mblk]) : "memory");
            } while (v < target);
        }
        __syncthreads();

        // ---- issue BOTH K-halves of the h A-tile as separate groups ----
        const __nv_bfloat16* hsrc = (t == 0) ? g_hz
                                             : g_hb + (size_t)(t - 1) * BPAD * HID;
#pragma unroll
        for (int it = 0; it < 16; it++) {          // half 0: k [0,256)
            int idx = tid + 256 * it;
            int r = idx >> 5, ch = idx & 31;
            const __nv_bfloat16* src = hsrc + (size_t)(m0 + r) * HID + ch * 8;
            uint32_t dst = (uint32_t)__cvta_generic_to_shared(&As[r * ST + ch * 8]);
            asm volatile("cp.async.cg.shared.global [%0], [%1], 16;" :: "r"(dst), "l"(src));
        }
        asm volatile("cp.async.commit_group;" ::: "memory");
#pragma unroll
        for (int it = 0; it < 16; it++) {          // half 1: k [256,512)
            int idx = tid + 256 * it;
            int r = idx >> 5, ch = (idx & 31) + 32;
            const __nv_bfloat16* src = hsrc + (size_t)(m0 + r) * HID + ch * 8;
            uint32_t dst = (uint32_t)__cvta_generic_to_shared(&As[r * ST + ch * 8]);
            asm volatile("cp.async.cg.shared.global [%0], [%1], 16;" :: "r"(dst), "l"(src));
        }
        asm volatile("cp.async.commit_group;" ::: "memory");

        float acc[2][4][4];
#pragma unroll
        for (int mf = 0; mf < 2; mf++)
#pragma unroll
            for (int nf = 0; nf < 4; nf++)
#pragma unroll
                for (int r = 0; r < 4; r++) acc[mf][nf][r] = 0.f;

        // ---- half 0 compute (half 1 load in flight) ----
        asm volatile("cp.async.wait_group 1;" ::: "memory");
        __syncthreads();
#pragma unroll
        for (int kk = 0; kk < 16; kk++) {
            uint32_t a0[4], a1[4], b01[4], b23[4];
            ldsm_x4(a0, aaddr[0] + kk * 32);
            ldsm_x4(a1, aaddr[1] + kk * 32);
            ldsm_x4(b01, baddr[0] + kk * 32);
            ldsm_x4(b23, baddr[1] + kk * 32);
            mma_bf16(acc[0][0], a0, b01);     mma_bf16(acc[0][1], a0, b01 + 2);
            mma_bf16(acc[0][2], a0, b23);     mma_bf16(acc[0][3], a0, b23 + 2);
            mma_bf16(acc[1][0], a1, b01);     mma_bf16(acc[1][1], a1, b01 + 2);
            mma_bf16(acc[1][2], a1, b23);     mma_bf16(acc[1][3], a1, b23 + 2);
        }
        // ---- half 1 compute ----
        asm volatile("cp.async.wait_group 0;" ::: "memory");
        __syncthreads();
#pragma unroll
        for (int kk = 16; kk < 32; kk++) {
            uint32_t a0[4], a1[4], b01[4], b23[4];
            ldsm_x4(a0, aaddr[0] + kk * 32);
            ldsm_x4(a1, aaddr[1] + kk * 32);
            ldsm_x4(b01, baddr[0] + kk * 32);
            ldsm_x4(b23, baddr[1] + kk * 32);
            mma_bf16(acc[0][0], a0, b01);     mma_bf16(acc[0][1], a0, b01 + 2);
            mma_bf16(acc[0][2], a0, b23);     mma_bf16(acc[0][3], a0, b23 + 2);
            mma_bf16(acc[1][0], a1, b01);     mma_bf16(acc[1][1], a1, b01 + 2);
            mma_bf16(acc[1][2], a1, b23);     mma_bf16(acc[1][3], a1, b23 + 2);
        }

        // ---- epilogue: + xg, + bias, gate exchange, cell update -> smem staging ----
#pragma unroll
        for (int mf = 0; mf < 2; mf++) {
            const int row = mw * 32 + mf * 16 + gr;
#pragma unroll
            for (int nf = 0; nf < 4; nf++) {
                float2 x0 = __bfloat1622float2(*(__nv_bfloat162*)&xr[mf][nf][0]);
                float2 x1 = __bfloat1622float2(*(__nv_bfloat162*)&xr[mf][nf][1]);
                float b0 = even ? pb4[nf].x : pb4[nf].z;
                float b1 = even ? pb4[nf].y : pb4[nf].w;
                float v0 = acc[mf][nf][0] + x0.x + b0;
                float v1 = acc[mf][nf][1] + x0.y + b1;
                float v2 = acc[mf][nf][2] + x1.x + b0;
                float v3 = acc[mf][nf][3] + x1.y + b1;
                float s0 = __shfl_xor_sync(0xffffffffu, v0, 1);
                float s1 = __shfl_xor_sync(0xffffffffu, v1, 1);
                float s2 = __shfl_xor_sync(0xffffffffu, v2, 1);
                float s3 = __shfl_xor_sync(0xffffffffu, v3, 1);
                if (even) {
                    const int jc = nw * 8 + 2 * nf + (tg >> 1);
                    float ig0 = fast_sigmoid(v0), fg0 = fast_sigmoid(v1);
                    float gt0 = fast_tanh(s0),    ot0 = fast_sigmoid(s1);
                    float c0 = fg0 * creg[mf][nf][0] + ig0 * gt0;
                    creg[mf][nf][0] = c0;
                    Hsb[row * HS2 + jc] = __float2bfloat16_rn(ot0 * fast_tanh(c0));
                    float ig1 = fast_sigmoid(v2), fg1 = fast_sigmoid(v3);
                    float gt1 = fast_tanh(s2),    ot1 = fast_sigmoid(s3);
                    float c1 = fg1 * creg[mf][nf][1] + ig1 * gt1;
                    creg[mf][nf][1] = c1;
                    Hsb[(row + 8) * HS2 + jc] = __float2bfloat16_rn(ot1 * fast_tanh(c1));
                }
            }
        }
        __syncthreads();

        // ---- coalesced flush: 256 x 16B stores ----
        {
            const int row = tid >> 1, half = tid & 1;
            uint4 v = *(uint4*)&Hsb[row * HS2 + half * 8];
            *(uint4*)(g_hb + (size_t)t * BPAD * HID +
                      (size_t)(m0 + row) * HID + blockIdx.y * 16 + half * 8) = v;
        }
        __threadfence();
        __syncthreads();
        if (tid == 0) atomicAdd(&g_bar[mblk], 1u);
    }
}

// -------------------------------------------------------------------------
// FC (bf16 mma): out[b][t][o] = sigmoid(g_hb[t][b] . W_fc[o] + b_fc[o])
// -------------------------------------------------------------------------
#define XA_STRIDE 40
__global__ __launch_bounds__(256) void fc_gemm_kernel(
    const float* __restrict__ bfc,
    float* __restrict__ out)
{
    __shared__ __nv_bfloat16 As[2][128 * XA_STRIDE];
    __shared__ __nv_bfloat16 Bs[2][128 * XA_STRIDE];
    const int tid = threadIdx.x;
    const int lid = tid & 31, wid = tid >> 5;
    const int tg = lid & 3, gr = lid >> 2;
    const int mw = wid & 3, nw = wid >> 2;
    const size_t R0 = (size_t)blockIdx.x * 128;

    float acc[2][8][4];
#pragma unroll
    for (int mf = 0; mf < 2; mf++)
#pragma unroll
        for (int nf = 0; nf < 8; nf++)
#pragma unroll
            for (int r = 0; r < 4; r++) acc[mf][nf][r] = 0.f;

    auto load_stage = [&](int s) {
        const int buf = s & 1;
        const int k0 = s * 32;
#pragma unroll
        for (int it = 0; it < 2; it++) {
            int idx = tid + 256 * it;
            int r = idx >> 2, ch = idx & 3;
            const __nv_bfloat16* src = g_hb + (R0 + r) * HID + k0 + ch * 8;
            uint32_t dst = (uint32_t)__cvta_generic_to_shared(&As[buf][r * XA_STRIDE + ch * 8]);
            asm volatile("cp.async.cg.shared.global [%0], [%1], 16;" :: "r"(dst), "l"(src));
        }
#pragma unroll
        for (int it = 0; it < 2; it++) {
            int idx = tid + 256 * it;
            int r = idx >> 2, ch = idx & 3;
            const __nv_bfloat16* src = g_Wf + (size_t)r * 512 + k0 + ch * 8;
            uint32_t dst = (uint32_t)__cvta_generic_to_shared(&Bs[buf][r * XA_STRIDE + ch * 8]);
            asm volatile("cp.async.cg.shared.global [%0], [%1], 16;" :: "r"(dst), "l"(src));
        }
        asm volatile("cp.async.commit_group;" ::: "memory");
    };

    load_stage(0);
#pragma unroll 1
    for (int s = 0; s < 16; s++) {
        if (s + 1 < 16) {
            load_stage(s + 1);
            asm volatile("cp.async.wait_group 1;" ::: "memory");
        } else {
            asm volatile("cp.async.wait_group 0;" ::: "memory");
        }
        __syncthreads();
        const int buf = s & 1;
        const __nv_bfloat16* Ab = &As[buf][(mw * 32) * XA_STRIDE];
        const __nv_bfloat16* Bb = &Bs[buf][(nw * 64) * XA_STRIDE];
#pragma unroll
        for (int ks = 0; ks < 2; ks++) {
            const int k = ks * 16 + tg * 2;
            uint32_t a[2][4];
#pragma unroll
            for (int mf = 0; mf < 2; mf++) {
                const __nv_bfloat16* p = Ab + (mf * 16 + gr) * XA_STRIDE + k;
                a[mf][0] = *(const uint32_t*)p;
                a[mf][1] = *(const uint32_t*)(p + 8 * XA_STRIDE);
                a[mf][2] = *(const uint32_t*)(p + 8);
                a[mf][3] = *(const uint32_t*)(p + 8 * XA_STRIDE + 8);
            }
#pragma unroll
            for (int nf = 0; nf < 8; nf++) {
                const __nv_bfloat16* p = Bb + (nf * 8 + gr) * XA_STRIDE + k;
                uint32_t b[2];
                b[0] = *(const uint32_t*)p;
                b[1] = *(const uint32_t*)(p + 8);
#pragma unroll
                for (int mf = 0; mf < 2; mf++) mma_bf16(acc[mf][nf], a[mf], b);
            }
        }
        __syncthreads();
    }

#pragma unroll
    for (int mf = 0; mf < 2; mf++)
#pragma unroll
        for (int nf = 0; nf < 8; nf++) {
            const int c = nw * 64 + nf * 8 + 2 * tg;
            if (c >= NOUT) continue;
#pragma unroll
            for (int half = 0; half < 2; half++) {
                size_t R = R0 + mw * 32 + mf * 16 + gr + half * 8;
                int t = (int)(R >> 9);
                int b = (int)(R & 511);
                if (b < BATCH) {
                    float* dst = out + ((size_t)b * TSTEPS + t) * NOUT + c;
                    dst[0] = fast_sigmoid(acc[mf][nf][half * 2 + 0] + bfc[c]);
                    dst[1] = fast_sigmoid(acc[mf][nf][half * 2 + 1] + bfc[c + 1]);
                }
            }
        }
}

// -------------------------------------------------------------------------
extern "C" void kernel_launch(void* const* d_in, const int* in_sizes, int n_in,
                              void* d_out, int out_size) {
    const float* inp  = (const float*)d_in[0];
    const float* Wih  = (const float*)d_in[1];
    const float* Whh  = (const float*)d_in[2];
    const float* bih  = (const float*)d_in[3];
    const float* bhh  = (const float*)d_in[4];
    const float* Wfc  = (const float*)d_in[5];
    const float* bfc  = (const float*)d_in[6];
    float* out = (float*)d_out;

    cudaFuncSetAttribute(lstm_persist_kernel,
                         cudaFuncAttributeMaxDynamicSharedMemorySize, PERSIST_SMEM);
    cudaFuncSetAttribute(xg_gemm_kernel,
                         cudaFuncAttributeMaxDynamicSharedMemorySize, XG_SMEM);

    zero_state_kernel<<<512, 256>>>();
    {
        long long total = (long long)TSTEPS * BATCH * EMB;
        int blocks = (int)((total + 255) / 256);
        prep_xbf_kernel<<<blocks, 256>>>(inp);
    }
    zero_xbf_pad_kernel<<<(TSTEPS * 12 * EMB / 2 + 255) / 256, 256>>>();
    prep_w_kernel<<<(2048 * 1024) / 256, 256>>>(Wih, Whh, bih, bhh, Wfc);

    xg_gemm_kernel<<<dim3(MROWS / 128, 16), 256, XG_SMEM>>>();

    lstm_persist_kernel<<<dim3(4, 32), 256, PERSIST_SMEM>>>();

    fc_gemm_kernel<<<1024, 256>>>(bfc, out);
}

// round 10
// speedup vs baseline: 7.9322x; 1.0009x over previous
#include <cuda_runtime.h>
#include <cuda_bf16.h>
#include <math.h>
#include <stdint.h>

#define BATCH 500
#define BPAD 512
#define TSTEPS 256
#define EMB 512
#define HID 512
#define NOUT 100
#define TBSTRIDE (TSTEPS * EMB)
#define MROWS (TSTEPS * BPAD)

// ------------------------- device globals (scratch) -------------------------
__device__ __nv_bfloat16 g_xbf[(size_t)MROWS * EMB];        // 134MB  [t*512+b][e]
__device__ __nv_bfloat16 g_Wx[2048 * 512];                  // permuted Wih bf16
__device__ __nv_bfloat16 g_Wh[2048 * 512];                  // permuted Whh bf16
__device__ __nv_bfloat16 g_Wf[128 * 512];                   // Wfc bf16, padded
__device__ float g_pb[2048];                                // permuted bias
__device__ __nv_bfloat16 g_hb[(size_t)TSTEPS * BPAD * HID]; // 134MB bf16 h, t-indexed
__device__ __nv_bfloat16 g_hz[BPAD * HID];                  // zero h slab for t=0
__device__ unsigned g_bar[4];                               // per-m-group counters

__device__ __forceinline__ float fast_sigmoid(float x) {
    return 1.f / (1.f + __expf(-x));
}
__device__ __forceinline__ float fast_tanh(float x) {
    float ax = fabsf(x);
    float e = __expf(-2.f * ax);
    float r = (1.f - e) / (1.f + e);
    return copysignf(r, x);
}

// ------------------------- init / prep -------------------------
__global__ void zero_state_kernel() {
    int idx = blockIdx.x * blockDim.x + threadIdx.x;
    if (idx < BPAD * HID / 2) ((uint32_t*)g_hz)[idx] = 0u;
    if (idx < 4) g_bar[idx] = 0u;
}

__global__ void prep_xbf_kernel(const float* __restrict__ inp) {
    long long idx = (long long)blockIdx.x * blockDim.x + threadIdx.x;
    if (idx >= (long long)TSTEPS * BATCH * EMB) return;
    int e = (int)(idx & 511);
    long long r = idx >> 9;
    int b = (int)(r % BATCH);
    int t = (int)(r / BATCH);
    float v = inp[(size_t)b * TBSTRIDE + (size_t)t * EMB + e];
    g_xbf[((size_t)t * BPAD + b) * EMB + e] = __float2bfloat16_rn(v);
}

__global__ void zero_xbf_pad_kernel() {
    int idx = blockIdx.x * blockDim.x + threadIdx.x;
    int total = TSTEPS * 12 * EMB / 2;
    if (idx >= total) return;
    int per_t = 12 * EMB / 2;
    int t = idx / per_t;
    int o = idx - t * per_t;
    ((uint32_t*)(g_xbf + ((size_t)t * BPAD + BATCH) * EMB))[o] = 0u;
}

__global__ void prep_w_kernel(const float* __restrict__ Wih,
                              const float* __restrict__ Whh,
                              const float* __restrict__ bih,
                              const float* __restrict__ bhh,
                              const float* __restrict__ Wfc) {
    int idx = blockIdx.x * blockDim.x + threadIdx.x;
    int np = idx >> 10;
    int k  = idx & 1023;
    int j = np >> 2, gate = np & 3;
    int n = gate * HID + j;
    if (k < 512) g_Wx[np * 512 + k] = __float2bfloat16_rn(Wih[(size_t)n * EMB + k]);
    else         g_Wh[np * 512 + (k - 512)] = __float2bfloat16_rn(Whh[(size_t)n * HID + (k - 512)]);
    if (idx < 2048) {
        int jj = idx >> 2, gg = idx & 3;
        g_pb[idx] = bih[gg * HID + jj] + bhh[gg * HID + jj];
    }
    if (idx < 128 * 512) {
        int fn = idx >> 9, fk = idx & 511;
        g_Wf[idx] = (fn < NOUT) ? __float2bfloat16_rn(Wfc[(size_t)fn * 512 + fk])
                                : __float2bfloat16_rn(0.f);
    }
}

// ------------------------- mma / ldmatrix helpers -------------------------
__device__ __forceinline__ void mma_bf16(float* d, const uint32_t* a, const uint32_t* b) {
    asm volatile(
        "mma.sync.aligned.m16n8k16.row.col.f32.bf16.bf16.f32 "
        "{%0,%1,%2,%3}, {%4,%5,%6,%7}, {%8,%9}, {%0,%1,%2,%3};"
        : "+f"(d[0]), "+f"(d[1]), "+f"(d[2]), "+f"(d[3])
        : "r"(a[0]), "r"(a[1]), "r"(a[2]), "r"(a[3]), "r"(b[0]), "r"(b[1]));
}
__device__ __forceinline__ void ldsm_x4(uint32_t* r, uint32_t addr) {
    asm volatile("ldmatrix.sync.aligned.m8n8.x4.shared.b16 {%0,%1,%2,%3}, [%4];"
                 : "=r"(r[0]), "=r"(r[1]), "=r"(r[2]), "=r"(r[3]) : "r"(addr));
}

// -------------------------------------------------------------------------
// Persistent fused LSTM: 128 CTAs (4 m-groups x 32 n-tiles), 256 steps.
// Per step: X-phase (x_t @ Wx, before barrier) + H-phase (h_{t-1} @ Wh).
// Wx+Wh slices resident in smem; A streams as 4 K-quarters, 2 buffers.
// -------------------------------------------------------------------------
#define ST 520                                  // W row stride (bf16)
#define AST 136                                 // A quarter row stride (bf16)
#define ABUF_BYTES (128 * AST * 2)              // 34816
#define HS2 24
#define OFF_WX 0
#define OFF_WH (64 * ST * 2)                    // 66560
#define OFF_A  (2 * 64 * ST * 2)                // 133120
#define OFF_HS (OFF_A + 2 * ABUF_BYTES)         // 202752
#define PERSIST_SMEM (OFF_HS + 128 * HS2 * 2)   // 208896

__global__ __launch_bounds__(256) void lstm_persist_kernel() {
    extern __shared__ char sm[];
    __nv_bfloat16* Hsb = (__nv_bfloat16*)(sm + OFF_HS);

    const int tid = threadIdx.x;
    const int lid = tid & 31, wid = tid >> 5;
    const int tg = lid & 3, gr = lid >> 2;
    const int mw = wid & 3, nw = wid >> 2;
    const int mblk = blockIdx.x;
    const int m0 = mblk * 128;
    const int n0 = blockIdx.y * 64;
    const bool even = (tg & 1) == 0;

    // ---- Wx and Wh slices (64 rows x 512 bf16 each) into smem once ----
#pragma unroll
    for (int it = 0; it < 16; it++) {
        int idx = tid + 256 * it;
        int r = idx >> 6, ch = idx & 63;
        const __nv_bfloat16* src = g_Wx + (size_t)(n0 + r) * 512 + ch * 8;
        uint32_t dst = (uint32_t)__cvta_generic_to_shared(sm + OFF_WX + (r * ST + ch * 8) * 2);
        asm volatile("cp.async.cg.shared.global [%0], [%1], 16;" :: "r"(dst), "l"(src));
    }
#pragma unroll
    for (int it = 0; it < 16; it++) {
        int idx = tid + 256 * it;
        int r = idx >> 6, ch = idx & 63;
        const __nv_bfloat16* src = g_Wh + (size_t)(n0 + r) * 512 + ch * 8;
        uint32_t dst = (uint32_t)__cvta_generic_to_shared(sm + OFF_WH + (r * ST + ch * 8) * 2);
        asm volatile("cp.async.cg.shared.global [%0], [%1], 16;" :: "r"(dst), "l"(src));
    }
    asm volatile("cp.async.commit_group;" ::: "memory");
    asm volatile("cp.async.wait_group 0;" ::: "memory");
    __syncthreads();

    // ---- ldmatrix base addresses ----
    uint32_t aaddr[2][2];        // [buf][mf]
    uint32_t bxaddr[2], bhaddr[2];
    {
        const uint32_t smbase = (uint32_t)__cvta_generic_to_shared(sm);
        const int arow = mw * 32 + (lid & 15);
        const int acol = (lid >> 4) << 3;
#pragma unroll
        for (int buf = 0; buf < 2; buf++)
#pragma unroll
            for (int mf = 0; mf < 2; mf++)
                aaddr[buf][mf] = smbase + OFF_A + buf * ABUF_BYTES
                               + (uint32_t)((arow + mf * 16) * AST + acol) * 2;
        const int brow = nw * 32 + ((lid >> 4) << 3) + (lid & 7);
        const int bcol = ((lid >> 3) & 1) << 3;
#pragma unroll
        for (int p = 0; p < 2; p++) {
            bxaddr[p] = smbase + OFF_WX + (uint32_t)((brow + p * 16) * ST + bcol) * 2;
            bhaddr[p] = smbase + OFF_WH + (uint32_t)((brow + p * 16) * ST + bcol) * 2;
        }
    }

    float4 pb4[4];
#pragma unroll
    for (int nf = 0; nf < 4; nf++) {
        int jc = nw * 8 + 2 * nf + (tg >> 1);
        pb4[nf] = *(const float4*)&g_pb[n0 + jc * 4];
    }

    float creg[2][4][2];
#pragma unroll
    for (int mf = 0; mf < 2; mf++)
#pragma unroll
        for (int nf = 0; nf < 4; nf++) { creg[mf][nf][0] = 0.f; creg[mf][nf][1] = 0.f; }

    float acc[2][4][4];

    // quarter loader: 128 rows x 128 cols bf16 (row stride 512 in gmem)
    auto load_q = [&](const __nv_bfloat16* base, int q, int buf) {
#pragma unroll
        for (int it = 0; it < 8; it++) {
            int idx = tid + 256 * it;
            int r = idx >> 4, ch = idx & 15;
            const __nv_bfloat16* src = base + (size_t)r * 512 + q * 128 + ch * 8;
            uint32_t dst = (uint32_t)__cvta_generic_to_shared(
                sm + OFF_A + buf * ABUF_BYTES + (r * AST + ch * 8) * 2);
            asm volatile("cp.async.cg.shared.global [%0], [%1], 16;" :: "r"(dst), "l"(src));
        }
        asm volatile("cp.async.commit_group;" ::: "memory");
    };

    auto mma_q = [&](int q, int buf, const uint32_t* baddr) {
#pragma unroll
        for (int kkl = 0; kkl < 8; kkl++) {
            uint32_t a0[4], a1[4], b01[4], b23[4];
            ldsm_x4(a0, aaddr[buf][0] + kkl * 32);
            ldsm_x4(a1, aaddr[buf][1] + kkl * 32);
            const int kg = (q * 8 + kkl) * 32;
            ldsm_x4(b01, baddr[0] + kg);
            ldsm_x4(b23, baddr[1] + kg);
            mma_bf16(acc[0][0], a0, b01);     mma_bf16(acc[0][1], a0, b01 + 2);
            mma_bf16(acc[0][2], a0, b23);     mma_bf16(acc[0][3], a0, b23 + 2);
            mma_bf16(acc[1][0], a1, b01);     mma_bf16(acc[1][1], a1, b01 + 2);
            mma_bf16(acc[1][2], a1, b23);     mma_bf16(acc[1][3], a1, b23 + 2);
        }
    };

    auto phase = [&](const __nv_bfloat16* base, const uint32_t* baddr) {
        load_q(base, 0, 0);
        load_q(base, 1, 1);
        asm volatile("cp.async.wait_group 1;" ::: "memory");
        __syncthreads();
        mma_q(0, 0, baddr);
        __syncthreads();
        load_q(base, 2, 0);
        asm volatile("cp.async.wait_group 1;" ::: "memory");
        __syncthreads();
        mma_q(1, 1, baddr);
        __syncthreads();
        load_q(base, 3, 1);
        asm volatile("cp.async.wait_group 1;" ::: "memory");
        __syncthreads();
        mma_q(2, 0, baddr);
        asm volatile("cp.async.wait_group 0;" ::: "memory");
        __syncthreads();
        mma_q(3, 1, baddr);
        __syncthreads();
    };

#pragma unroll 1
    for (int t = 0; t < TSTEPS; t++) {
#pragma unroll
        for (int mf = 0; mf < 2; mf++)
#pragma unroll
            for (int nf = 0; nf < 4; nf++)
#pragma unroll
                for (int r = 0; r < 4; r++) acc[mf][nf][r] = 0.f;

        // ---- X-phase: x_t @ Wx (no cross-CTA dependency; hides barrier) ----
        phase(g_xbf + ((size_t)t * BPAD + m0) * EMB, bxaddr);

        // ---- barrier: all 32 CTAs of this m-group finished step t-1 ----
        if (tid == 0 && t > 0) {
            const unsigned target = 32u * (unsigned)t;
            unsigned v;
            do {
                asm volatile("ld.acquire.gpu.global.u32 %0, [%1];"
                             : "=r"(v) : "l"(&g_bar[mblk]) : "memory");
            } while (v < target);
        }
        __syncthreads();

        // ---- H-phase: h_{t-1} @ Wh ----
        const __nv_bfloat16* hsrc = (t == 0) ? (g_hz + (size_t)m0 * HID)
                                             : (g_hb + ((size_t)(t - 1) * BPAD + m0) * HID);
        phase(hsrc, bhaddr);

        // ---- epilogue: + bias, gate exchange, cell update -> smem staging ----
#pragma unroll
        for (int mf = 0; mf < 2; mf++) {
            const int row = mw * 32 + mf * 16 + gr;
#pragma unroll
            for (int nf = 0; nf < 4; nf++) {
                float b0 = even ? pb4[nf].x : pb4[nf].z;
                float b1 = even ? pb4[nf].y : pb4[nf].w;
                float v0 = acc[mf][nf][0] + b0;
                float v1 = acc[mf][nf][1] + b1;
                float v2 = acc[mf][nf][2] + b0;
                float v3 = acc[mf][nf][3] + b1;
                float s0 = __shfl_xor_sync(0xffffffffu, v0, 1);
                float s1 = __shfl_xor_sync(0xffffffffu, v1, 1);
                float s2 = __shfl_xor_sync(0xffffffffu, v2, 1);
                float s3 = __shfl_xor_sync(0xffffffffu, v3, 1);
                if (even) {
                    const int jc = nw * 8 + 2 * nf + (tg >> 1);
                    float ig0 = fast_sigmoid(v0), fg0 = fast_sigmoid(v1);
                    float gt0 = fast_tanh(s0),    ot0 = fast_sigmoid(s1);
                    float c0 = fg0 * creg[mf][nf][0] + ig0 * gt0;
                    creg[mf][nf][0] = c0;
                    Hsb[row * HS2 + jc] = __float2bfloat16_rn(ot0 * fast_tanh(c0));
                    float ig1 = fast_sigmoid(v2), fg1 = fast_sigmoid(v3);
                    float gt1 = fast_tanh(s2),    ot1 = fast_sigmoid(s3);
                    float c1 = fg1 * creg[mf][nf][1] + ig1 * gt1;
                    creg[mf][nf][1] = c1;
                    Hsb[(row + 8) * HS2 + jc] = __float2bfloat16_rn(ot1 * fast_tanh(c1));
                }
            }
        }
        __syncthreads();

        // ---- coalesced flush: 256 x 16B stores ----
        {
            const int row = tid >> 1, half = tid & 1;
            uint4 v = *(uint4*)&Hsb[row * HS2 + half * 8];
            *(uint4*)(g_hb + (size_t)t * BPAD * HID +
                      (size_t)(m0 + row) * HID + blockIdx.y * 16 + half * 8) = v;
        }
        __threadfence();
        __syncthreads();
        if (tid == 0) atomicAdd(&g_bar[mblk], 1u);
    }
}

// -------------------------------------------------------------------------
// FC (bf16 mma): out[b][t][o] = sigmoid(g_hb[t][b] . W_fc[o] + b_fc[o])
// -------------------------------------------------------------------------
#define XA_STRIDE 40
__global__ __launch_bounds__(256) void fc_gemm_kernel(
    const float* __restrict__ bfc,
    float* __restrict__ out)
{
    __shared__ __nv_bfloat16 As[2][128 * XA_STRIDE];
    __shared__ __nv_bfloat16 Bs[2][128 * XA_STRIDE];
    const int tid = threadIdx.x;
    const int lid = tid & 31, wid = tid >> 5;
    const int tg = lid & 3, gr = lid >> 2;
    const int mw = wid & 3, nw = wid >> 2;
    const size_t R0 = (size_t)blockIdx.x * 128;

    float acc[2][8][4];
#pragma unroll
    for (int mf = 0; mf < 2; mf++)
#pragma unroll
        for (int nf = 0; nf < 8; nf++)
#pragma unroll
            for (int r = 0; r < 4; r++) acc[mf][nf][r] = 0.f;

    auto load_stage = [&](int s) {
        const int buf = s & 1;
        const int k0 = s * 32;
#pragma unroll
        for (int it = 0; it < 2; it++) {
            int idx = tid + 256 * it;
            int r = idx >> 2, ch = idx & 3;
            const __nv_bfloat16* src = g_hb + (R0 + r) * HID + k0 + ch * 8;
            uint32_t dst = (uint32_t)__cvta_generic_to_shared(&As[buf][r * XA_STRIDE + ch * 8]);
            asm volatile("cp.async.cg.shared.global [%0], [%1], 16;" :: "r"(dst), "l"(src));
        }
#pragma unroll
        for (int it = 0; it < 2; it++) {
            int idx = tid + 256 * it;
            int r = idx >> 2, ch = idx & 3;
            const __nv_bfloat16* src = g_Wf + (size_t)r * 512 + k0 + ch * 8;
            uint32_t dst = (uint32_t)__cvta_generic_to_shared(&Bs[buf][r * XA_STRIDE + ch * 8]);
            asm volatile("cp.async.cg.shared.global [%0], [%1], 16;" :: "r"(dst), "l"(src));
        }
        asm volatile("cp.async.commit_group;" ::: "memory");
    };

    load_stage(0);
#pragma unroll 1
    for (int s = 0; s < 16; s++) {
        if (s + 1 < 16) {
            load_stage(s + 1);
            asm volatile("cp.async.wait_group 1;" ::: "memory");
        } else {
            asm volatile("cp.async.wait_group 0;" ::: "memory");
        }
        __syncthreads();
        const int buf = s & 1;
        const __nv_bfloat16* Ab = &As[buf][(mw * 32) * XA_STRIDE];
        const __nv_bfloat16* Bb = &Bs[buf][(nw * 64) * XA_STRIDE];
#pragma unroll
        for (int ks = 0; ks < 2; ks++) {
            const int k = ks * 16 + tg * 2;
            uint32_t a[2][4];
#pragma unroll
            for (int mf = 0; mf < 2; mf++) {
                const __nv_bfloat16* p = Ab + (mf * 16 + gr) * XA_STRIDE + k;
                a[mf][0] = *(const uint32_t*)p;
                a[mf][1] = *(const uint32_t*)(p + 8 * XA_STRIDE);
                a[mf][2] = *(const uint32_t*)(p + 8);
                a[mf][3] = *(const uint32_t*)(p + 8 * XA_STRIDE + 8);
            }
#pragma unroll
            for (int nf = 0; nf < 8; nf++) {
                const __nv_bfloat16* p = Bb + (nf * 8 + gr) * XA_STRIDE + k;
                uint32_t b[2];
                b[0] = *(const uint32_t*)p;
                b[1] = *(const uint32_t*)(p + 8);
#pragma unroll
                for (int mf = 0; mf < 2; mf++) mma_bf16(acc[mf][nf], a[mf], b);
            }
        }
        __syncthreads();
    }

#pragma unroll
    for (int mf = 0; mf < 2; mf++)
#pragma unroll
        for (int nf = 0; nf < 8; nf++) {
            const int c = nw * 64 + nf * 8 + 2 * tg;
            if (c >= NOUT) continue;
#pragma unroll
            for (int half = 0; half < 2; half++) {
                size_t R = R0 + mw * 32 + mf * 16 + gr + half * 8;
                int t = (int)(R >> 9);
                int b = (int)(R & 511);
                if (b < BATCH) {
                    float* dst = out + ((size_t)b * TSTEPS + t) * NOUT + c;
                    dst[0] = fast_sigmoid(acc[mf][nf][half * 2 + 0] + bfc[c]);
                    dst[1] = fast_sigmoid(acc[mf][nf][half * 2 + 1] + bfc[c + 1]);
                }
            }
        }
}

// -------------------------------------------------------------------------
extern "C" void kernel_launch(void* const* d_in, const int* in_sizes, int n_in,
                              void* d_out, int out_size) {
    const float* inp  = (const float*)d_in[0];
    const float* Wih  = (const float*)d_in[1];
    const float* Whh  = (const float*)d_in[2];
    const float* bih  = (const float*)d_in[3];
    const float* bhh  = (const float*)d_in[4];
    const float* Wfc  = (const float*)d_in[5];
    const float* bfc  = (const float*)d_in[6];
    float* out = (float*)d_out;

    cudaFuncSetAttribute(lstm_persist_kernel,
                         cudaFuncAttributeMaxDynamicSharedMemorySize, PERSIST_SMEM);

    zero_state_kernel<<<512, 256>>>();
    {
        long long total = (long long)TSTEPS * BATCH * EMB;
        int blocks = (int)((total + 255) / 256);
        prep_xbf_kernel<<<blocks, 256>>>(inp);
    }
    zero_xbf_pad_kernel<<<(TSTEPS * 12 * EMB / 2 + 255) / 256, 256>>>();
    prep_w_kernel<<<(2048 * 1024) / 256, 256>>>(Wih, Whh, bih, bhh, Wfc);

    lstm_persist_kernel<<<dim3(4, 32), 256, PERSIST_SMEM>>>();

    fc_gemm_kernel<<<1024, 256>>>(bfc, out);
}

// round 12
// speedup vs baseline: 8.1572x; 1.0284x over previous
#include <cuda_runtime.h>
#include <cuda_bf16.h>
#include <math.h>
#include <stdint.h>

#define BATCH 500
#define BPAD 512
#define TSTEPS 256
#define EMB 512
#define HID 512
#define NOUT 100
#define TBSTRIDE (TSTEPS * EMB)
#define MROWS (TSTEPS * BPAD)

// ------------------------- device globals (scratch) -------------------------
__device__ __nv_bfloat16 g_xbf[(size_t)MROWS * EMB];        // 134MB  [t*512+b][e]
__device__ __nv_bfloat16 g_Wx[2048 * 512];
__device__ __nv_bfloat16 g_Wh[2048 * 512];
__device__ __nv_bfloat16 g_Wf[128 * 512];
__device__ float g_pb[2048];
__device__ __nv_bfloat16 g_xg[(size_t)MROWS * 2048];        // 540MB xg bf16
__device__ __nv_bfloat16 g_hb[(size_t)TSTEPS * BPAD * HID]; // 134MB bf16 h, t-indexed
__device__ unsigned g_bar[4];

__device__ __forceinline__ float fast_sigmoid(float x) {
    return 1.f / (1.f + __expf(-x));
}
__device__ __forceinline__ float fast_tanh(float x) {
    float ax = fabsf(x);
    float e = __expf(-2.f * ax);
    float r = (1.f - e) / (1.f + e);
    return copysignf(r, x);
}

// ------------------------- init / prep -------------------------
__global__ void zero_state_kernel() {
    int idx = blockIdx.x * blockDim.x + threadIdx.x;
    if (idx < 4) g_bar[idx] = 0u;
}

__global__ void prep_xbf_kernel(const float* __restrict__ inp) {
    long long idx = (long long)blockIdx.x * blockDim.x + threadIdx.x;
    if (idx >= (long long)TSTEPS * BATCH * EMB) return;
    int e = (int)(idx & 511);
    long long r = idx >> 9;
    int b = (int)(r % BATCH);
    int t = (int)(r / BATCH);
    float v = inp[(size_t)b * TBSTRIDE + (size_t)t * EMB + e];
    g_xbf[((size_t)t * BPAD + b) * EMB + e] = __float2bfloat16_rn(v);
}

__global__ void zero_xbf_pad_kernel() {
    int idx = blockIdx.x * blockDim.x + threadIdx.x;
    int total = TSTEPS * 12 * EMB / 2;
    if (idx >= total) return;
    int per_t = 12 * EMB / 2;
    int t = idx / per_t;
    int o = idx - t * per_t;
    ((uint32_t*)(g_xbf + ((size_t)t * BPAD + BATCH) * EMB))[o] = 0u;
}

__global__ void prep_w_kernel(const float* __restrict__ Wih,
                              const float* __restrict__ Whh,
                              const float* __restrict__ bih,
                              const float* __restrict__ bhh,
                              const float* __restrict__ Wfc) {
    int idx = blockIdx.x * blockDim.x + threadIdx.x;
    int np = idx >> 10;
    int k  = idx & 1023;
    int j = np >> 2, gate = np & 3;
    int n = gate * HID + j;
    if (k < 512) g_Wx[np * 512 + k] = __float2bfloat16_rn(Wih[(size_t)n * EMB + k]);
    else         g_Wh[np * 512 + (k - 512)] = __float2bfloat16_rn(Whh[(size_t)n * HID + (k - 512)]);
    if (idx < 2048) {
        int jj = idx >> 2, gg = idx & 3;
        g_pb[idx] = bih[gg * HID + jj] + bhh[gg * HID + jj];
    }
    if (idx < 128 * 512) {
        int fn = idx >> 9, fk = idx & 511;
        g_Wf[idx] = (fn < NOUT) ? __float2bfloat16_rn(Wfc[(size_t)fn * 512 + fk])
                                : __float2bfloat16_rn(0.f);
    }
}

// ------------------------- mma / ldmatrix helpers -------------------------
__device__ __forceinline__ void mma_bf16(float* d, const uint32_t* a, const uint32_t* b) {
    asm volatile(
        "mma.sync.aligned.m16n8k16.row.col.f32.bf16.bf16.f32 "
        "{%0,%1,%2,%3}, {%4,%5,%6,%7}, {%8,%9}, {%0,%1,%2,%3};"
        : "+f"(d[0]), "+f"(d[1]), "+f"(d[2]), "+f"(d[3])
        : "r"(a[0]), "r"(a[1]), "r"(a[2]), "r"(a[3]), "r"(b[0]), "r"(b[1]));
}
__device__ __forceinline__ void ldsm_x4(uint32_t* r, uint32_t addr) {
    asm volatile("ldmatrix.sync.aligned.m8n8.x4.shared.b16 {%0,%1,%2,%3}, [%4];"
                 : "=r"(r[0]), "=r"(r[1]), "=r"(r[2]), "=r"(r[3]) : "r"(addr));
}

// -------------------------------------------------------------------------
// Big parallel GEMM: g_xg[131072][2048](bf16) = g_xbf @ g_Wx^T
// grid (16 n-tiles, 1024 m-tiles): n fastest -> A tile L2 reuse across wave.
// -------------------------------------------------------------------------
#define XS2 72
#define XBUF (128 * XS2)
#define XG_SMEM (4 * XBUF * 2)       // 73728

__global__ __launch_bounds__(256) void xg_gemm_kernel() {
    extern __shared__ __nv_bfloat16 xsm[];
    __nv_bfloat16* As = xsm;
    __nv_bfloat16* Bs = xsm + 2 * XBUF;
    const int tid = threadIdx.x;
    const int lid = tid & 31, wid = tid >> 5;
    const int tg = lid & 3, gr = lid >> 2;
    const int mw = wid & 3, nw = wid >> 2;
    const size_t R0 = (size_t)blockIdx.y * 128;
    const int n0 = blockIdx.x * 128;

    float acc[2][8][4];
#pragma unroll
    for (int mf = 0; mf < 2; mf++)
#pragma unroll
        for (int nf = 0; nf < 8; nf++)
#pragma unroll
            for (int r = 0; r < 4; r++) acc[mf][nf][r] = 0.f;

    uint32_t aA[2][2], bB[2][4];
    {
        const uint32_t abase = (uint32_t)__cvta_generic_to_shared(As);
        const uint32_t bbase = (uint32_t)__cvta_generic_to_shared(Bs);
        const int arow = mw * 32 + (lid & 15);
        const int acol = (lid >> 4) << 3;
        const int brb = nw * 64 + ((lid >> 4) << 3) + (lid & 7);
        const int bcol = ((lid >> 3) & 1) << 3;
#pragma unroll
        for (int buf = 0; buf < 2; buf++) {
#pragma unroll
            for (int mf = 0; mf < 2; mf++)
                aA[buf][mf] = abase + (uint32_t)(buf * XBUF + (arow + mf * 16) * XS2 + acol) * 2;
#pragma unroll
            for (int p = 0; p < 4; p++)
                bB[buf][p] = bbase + (uint32_t)(buf * XBUF + (brb + p * 16) * XS2 + bcol) * 2;
        }
    }

    auto load_stage = [&](int s) {
        const int buf = s & 1;
        const int k0 = s * 64;
#pragma unroll
        for (int it = 0; it < 4; it++) {
            int idx = tid + 256 * it;
            int r = idx >> 3, ch = idx & 7;
            const __nv_bfloat16* src = g_xbf + (R0 + r) * EMB + k0 + ch * 8;
            uint32_t dst = (uint32_t)__cvta_generic_to_shared(&As[buf * XBUF + r * XS2 + ch * 8]);
            asm volatile("cp.async.cg.shared.global [%0], [%1], 16;" :: "r"(dst), "l"(src));
        }
#pragma unroll
        for (int it = 0; it < 4; it++) {
            int idx = tid + 256 * it;
            int r = idx >> 3, ch = idx & 7;
            const __nv_bfloat16* src = g_Wx + (size_t)(n0 + r) * 512 + k0 + ch * 8;
            uint32_t dst = (uint32_t)__cvta_generic_to_shared(&Bs[buf * XBUF + r * XS2 + ch * 8]);
            asm volatile("cp.async.cg.shared.global [%0], [%1], 16;" :: "r"(dst), "l"(src));
        }
        asm volatile("cp.async.commit_group;" ::: "memory");
    };

    load_stage(0);
#pragma unroll 1
    for (int s = 0; s < 8; s++) {
        if (s + 1 < 8) {
            load_stage(s + 1);
            asm volatile("cp.async.wait_group 1;" ::: "memory");
        } else {
            asm volatile("cp.async.wait_group 0;" ::: "memory");
        }
        __syncthreads();
        const int buf = s & 1;
#pragma unroll
        for (int kk = 0; kk < 4; kk++) {
            uint32_t a0[4], a1[4];
            ldsm_x4(a0, aA[buf][0] + kk * 32);
            ldsm_x4(a1, aA[buf][1] + kk * 32);
#pragma unroll
            for (int p = 0; p < 4; p++) {
                uint32_t bb[4];
                ldsm_x4(bb, bB[buf][p] + kk * 32);
                mma_bf16(acc[0][2 * p],     a0, bb);
                mma_bf16(acc[0][2 * p + 1], a0, bb + 2);
                mma_bf16(acc[1][2 * p],     a1, bb);
                mma_bf16(acc[1][2 * p + 1], a1, bb + 2);
            }
        }
        __syncthreads();
    }

    uint32_t* xg32 = (uint32_t*)g_xg;
#pragma unroll
    for (int mf = 0; mf < 2; mf++)
#pragma unroll
        for (int nf = 0; nf < 8; nf++) {
            size_t R = R0 + mw * 32 + mf * 16 + gr;
            int c = n0 + nw * 64 + nf * 8 + 2 * tg;
            __nv_bfloat162 lo = __float22bfloat162_rn(make_float2(acc[mf][nf][0], acc[mf][nf][1]));
            __nv_bfloat162 hi = __float22bfloat162_rn(make_float2(acc[mf][nf][2], acc[mf][nf][3]));
            xg32[R * 1024 + (c >> 1)]       = *(uint32_t*)&lo;
            xg32[(R + 8) * 1024 + (c >> 1)] = *(uint32_t*)&hi;
        }
}

// -------------------------------------------------------------------------
// Persistent LSTM (H-GEMM only): 128 CTAs (4 m-groups x 32 n-tiles).
// Full h A-tile in smem, 4-quarter pipelined load; all-thread flag spin;
// release-atomic handoff. t=0 skips H-GEMM (h0 = 0).
// -------------------------------------------------------------------------
#define ST 520
#define HS2 24
#define OFF_WH 0
#define OFF_A  (64 * ST * 2)                    // 66560
#define OFF_HS (OFF_A + 128 * ST * 2)           // 199680
#define PERSIST_SMEM (OFF_HS + 128 * HS2 * 2)   // 205824

__global__ __launch_bounds__(256) void lstm_persist_kernel() {
    extern __shared__ char sm[];
    __nv_bfloat16* Hsb = (__nv_bfloat16*)(sm + OFF_HS);

    const int tid = threadIdx.x;
    const int lid = tid & 31, wid = tid >> 5;
    const int tg = lid & 3, gr = lid >> 2;
    const int mw = wid & 3, nw = wid >> 2;
    const int mblk = blockIdx.x;
    const int m0 = mblk * 128;
    const int n0 = blockIdx.y * 64;
    const bool even = (tg & 1) == 0;

    // ---- Wh slice (64 rows x 512 bf16) resident ----
#pragma unroll
    for (int it = 0; it < 16; it++) {
        int idx = tid + 256 * it;
        int r = idx >> 6, ch = idx & 63;
        const __nv_bfloat16* src = g_Wh + (size_t)(n0 + r) * 512 + ch * 8;
        uint32_t dst = (uint32_t)__cvta_generic_to_shared(sm + OFF_WH + (r * ST + ch * 8) * 2);
        asm volatile("cp.async.cg.shared.global [%0], [%1], 16;" :: "r"(dst), "l"(src));
    }
    asm volatile("cp.async.commit_group;" ::: "memory");
    asm volatile("cp.async.wait_group 0;" ::: "memory");
    __syncthreads();

    uint32_t aaddr[2], baddr[2];
    {
        const uint32_t smbase = (uint32_t)__cvta_generic_to_shared(sm);
        const int arow = mw * 32 + (lid & 15);
        const int acol = (lid >> 4) << 3;
#pragma unroll
        for (int mf = 0; mf < 2; mf++)
            aaddr[mf] = smbase + OFF_A + (uint32_t)((arow + mf * 16) * ST + acol) * 2;
        const int brow = nw * 32 + ((lid >> 4) << 3) + (lid & 7);
        const int bcol = ((lid >> 3) & 1) << 3;
#pragma unroll
        for (int p = 0; p < 2; p++)
            baddr[p] = smbase + OFF_WH + (uint32_t)((brow + p * 16) * ST + bcol) * 2;
    }

    float4 pb4[4];
#pragma unroll
    for (int nf = 0; nf < 4; nf++) {
        int jc = nw * 8 + 2 * nf + (tg >> 1);
        pb4[nf] = *(const float4*)&g_pb[n0 + jc * 4];
    }

    float creg[2][4][2];
#pragma unroll
    for (int mf = 0; mf < 2; mf++)
#pragma unroll
        for (int nf = 0; nf < 4; nf++) { creg[mf][nf][0] = 0.f; creg[mf][nf][1] = 0.f; }

    const uint32_t* xg32 = (const uint32_t*)g_xg;
    const int colu = (n0 + nw * 32 + 2 * tg) >> 1;

    float acc[2][4][4];

    // quarter loader: 128 rows x 128 bf16 cols = 2048 x 16B chunks
    auto load_q = [&](const __nv_bfloat16* hsrc, int q) {
#pragma unroll
        for (int it = 0; it < 8; it++) {
            int idx = tid + 256 * it;              // 2048 chunks
            int r = idx >> 4, ch = idx & 15;       // 128 rows x 16 chunks (FIXED)
            const __nv_bfloat16* src = hsrc + (size_t)r * HID + q * 128 + ch * 8;
            uint32_t dst = (uint32_t)__cvta_generic_to_shared(
                sm + OFF_A + (r * ST + q * 128 + ch * 8) * 2);
            asm volatile("cp.async.cg.shared.global [%0], [%1], 16;" :: "r"(dst), "l"(src));
        }
        asm volatile("cp.async.commit_group;" ::: "memory");
    };

    auto mma_q = [&](int q) {
#pragma unroll
        for (int kkl = 0; kkl < 8; kkl++) {
            const int kg = (q * 8 + kkl) * 32;
            uint32_t a0[4], a1[4], b01[4], b23[4];
            ldsm_x4(a0, aaddr[0] + kg);
            ldsm_x4(a1, aaddr[1] + kg);
            ldsm_x4(b01, baddr[0] + kg);
            ldsm_x4(b23, baddr[1] + kg);
            mma_bf16(acc[0][0], a0, b01);     mma_bf16(acc[0][1], a0, b01 + 2);
            mma_bf16(acc[0][2], a0, b23);     mma_bf16(acc[0][3], a0, b23 + 2);
            mma_bf16(acc[1][0], a1, b01);     mma_bf16(acc[1][1], a1, b01 + 2);
            mma_bf16(acc[1][2], a1, b23);     mma_bf16(acc[1][3], a1, b23 + 2);
        }
    };

#pragma unroll 1
    for (int t = 0; t < TSTEPS; t++) {
        // ---- xg prefetch (independent of flag) ----
        uint32_t xr[2][4][2];
        {
            const size_t rb = (size_t)t * BPAD + m0 + mw * 32 + gr;
#pragma unroll
            for (int mf = 0; mf < 2; mf++)
#pragma unroll
                for (int nf = 0; nf < 4; nf++) {
                    const size_t r0 = (rb + mf * 16) * 1024 + colu + nf * 4;
                    xr[mf][nf][0] = __ldg(xg32 + r0);
                    xr[mf][nf][1] = __ldg(xg32 + r0 + 8 * 1024);
                }
        }

#pragma unroll
        for (int mf = 0; mf < 2; mf++)
#pragma unroll
            for (int nf = 0; nf < 4; nf++)
#pragma unroll
                for (int r = 0; r < 4; r++) acc[mf][nf][r] = 0.f;

        if (t > 0) {
            // ---- all-thread spin on the m-group flag ----
            const unsigned target = 32u * (unsigned)t;
            unsigned v;
            do {
                asm volatile("ld.acquire.gpu.global.u32 %0, [%1];"
                             : "=r"(v) : "l"(&g_bar[mblk]) : "memory");
            } while (v < target);

            const __nv_bfloat16* hsrc = g_hb + ((size_t)(t - 1) * BPAD + m0) * HID;
            load_q(hsrc, 0); load_q(hsrc, 1); load_q(hsrc, 2); load_q(hsrc, 3);

            asm volatile("cp.async.wait_group 3;" ::: "memory");
            __syncthreads();
            mma_q(0);
            asm volatile("cp.async.wait_group 2;" ::: "memory");
            __syncthreads();
            mma_q(1);
            asm volatile("cp.async.wait_group 1;" ::: "memory");
            __syncthreads();
            mma_q(2);
            asm volatile("cp.async.wait_group 0;" ::: "memory");
            __syncthreads();
            mma_q(3);
        }

        // ---- epilogue: + xg, + bias, gate exchange, cell update -> Hsb ----
#pragma unroll
        for (int mf = 0; mf < 2; mf++) {
            const int row = mw * 32 + mf * 16 + gr;
#pragma unroll
            for (int nf = 0; nf < 4; nf++) {
                float2 x0 = __bfloat1622float2(*(__nv_bfloat162*)&xr[mf][nf][0]);
                float2 x1 = __bfloat1622float2(*(__nv_bfloat162*)&xr[mf][nf][1]);
                float b0 = even ? pb4[nf].x : pb4[nf].z;
                float b1 = even ? pb4[nf].y : pb4[nf].w;
                float v0 = acc[mf][nf][0] + x0.x + b0;
                float v1 = acc[mf][nf][1] + x0.y + b1;
                float v2 = acc[mf][nf][2] + x1.x + b0;
                float v3 = acc[mf][nf][3] + x1.y + b1;
                float s0 = __shfl_xor_sync(0xffffffffu, v0, 1);
                float s1 = __shfl_xor_sync(0xffffffffu, v1, 1);
                float s2 = __shfl_xor_sync(0xffffffffu, v2, 1);
                float s3 = __shfl_xor_sync(0xffffffffu, v3, 1);
                if (even) {
                    const int jc = nw * 8 + 2 * nf + (tg >> 1);
                    float ig0 = fast_sigmoid(v0), fg0 = fast_sigmoid(v1);
                    float gt0 = fast_tanh(s0),    ot0 = fast_sigmoid(s1);
                    float c0 = fg0 * creg[mf][nf][0] + ig0 * gt0;
                    creg[mf][nf][0] = c0;
                    Hsb[row * HS2 + jc] = __float2bfloat16_rn(ot0 * fast_tanh(c0));
                    float ig1 = fast_sigmoid(v2), fg1 = fast_sigmoid(v3);
                    float gt1 = fast_tanh(s2),    ot1 = fast_sigmoid(s3);
                    float c1 = fg1 * creg[mf][nf][1] + ig1 * gt1;
                    creg[mf][nf][1] = c1;
                    Hsb[(row + 8) * HS2 + jc] = __float2bfloat16_rn(ot1 * fast_tanh(c1));
                }
            }
        }
        __syncthreads();

        // ---- coalesced flush: 256 x 16B stores ----
        {
            const int row = tid >> 1, half = tid & 1;
            uint4 v = *(uint4*)&Hsb[row * HS2 + half * 8];
            *(uint4*)(g_hb + (size_t)t * BPAD * HID +
                      (size_t)(m0 + row) * HID + blockIdx.y * 16 + half * 8) = v;
        }
        __syncthreads();
        if (tid == 0) {
            asm volatile("red.release.gpu.global.add.u32 [%0], 1;"
                         :: "l"(&g_bar[mblk]) : "memory");
        }
    }
}

// -------------------------------------------------------------------------
// FC (bf16 mma): out[b][t][o] = sigmoid(g_hb[t][b] . W_fc[o] + b_fc[o])
// -------------------------------------------------------------------------
#define XA_STRIDE 40
__global__ __launch_bounds__(256) void fc_gemm_kernel(
    const float* __restrict__ bfc,
    float* __restrict__ out)
{
    __shared__ __nv_bfloat16 As[2][128 * XA_STRIDE];
    __shared__ __nv_bfloat16 Bs[2][128 * XA_STRIDE];
    const int tid = threadIdx.x;
    const int lid = tid & 31, wid = tid >> 5;
    const int tg = lid & 3, gr = lid >> 2;
    const int mw = wid & 3, nw = wid >> 2;
    const size_t R0 = (size_t)blockIdx.x * 128;

    float acc[2][8][4];
#pragma unroll
    for (int mf = 0; mf < 2; mf++)
#pragma unroll
        for (int nf = 0; nf < 8; nf++)
#pragma unroll
            for (int r = 0; r < 4; r++) acc[mf][nf][r] = 0.f;

    auto load_stage = [&](int s) {
        const int buf = s & 1;
        const int k0 = s * 32;
#pragma unroll
        for (int it = 0; it < 2; it++) {
            int idx = tid + 256 * it;
            int r = idx >> 2, ch = idx & 3;
            const __nv_bfloat16* src = g_hb + (R0 + r) * HID + k0 + ch * 8;
            uint32_t dst = (uint32_t)__cvta_generic_to_shared(&As[buf][r * XA_STRIDE + ch * 8]);
            asm volatile("cp.async.cg.shared.global [%0], [%1], 16;" :: "r"(dst), "l"(src));
        }
#pragma unroll
        for (int it = 0; it < 2; it++) {
            int idx = tid + 256 * it;
            int r = idx >> 2, ch = idx & 3;
            const __nv_bfloat16* src = g_Wf + (size_t)r * 512 + k0 + ch * 8;
            uint32_t dst = (uint32_t)__cvta_generic_to_shared(&Bs[buf][r * XA_STRIDE + ch * 8]);
            asm volatile("cp.async.cg.shared.global [%0], [%1], 16;" :: "r"(dst), "l"(src));
        }
        asm volatile("cp.async.commit_group;" ::: "memory");
    };

    load_stage(0);
#pragma unroll 1
    for (int s = 0; s < 16; s++) {
        if (s + 1 < 16) {
            load_stage(s + 1);
            asm volatile("cp.async.wait_group 1;" ::: "memory");
        } else {
            asm volatile("cp.async.wait_group 0;" ::: "memory");
        }
        __syncthreads();
        const int buf = s & 1;
        const __nv_bfloat16* Ab = &As[buf][(mw * 32) * XA_STRIDE];
        const __nv_bfloat16* Bb = &Bs[buf][(nw * 64) * XA_STRIDE];
#pragma unroll
        for (int ks = 0; ks < 2; ks++) {
            const int k = ks * 16 + tg * 2;
            uint32_t a[2][4];
#pragma unroll
            for (int mf = 0; mf < 2; mf++) {
                const __nv_bfloat16* p = Ab + (mf * 16 + gr) * XA_STRIDE + k;
                a[mf][0] = *(const uint32_t*)p;
                a[mf][1] = *(const uint32_t*)(p + 8 * XA_STRIDE);
                a[mf][2] = *(const uint32_t*)(p + 8);
                a[mf][3] = *(const uint32_t*)(p + 8 * XA_STRIDE + 8);
            }
#pragma unroll
            for (int nf = 0; nf < 8; nf++) {
                const __nv_bfloat16* p = Bb + (nf * 8 + gr) * XA_STRIDE + k;
                uint32_t b[2];
                b[0] = *(const uint32_t*)p;
                b[1] = *(const uint32_t*)(p + 8);
#pragma unroll
                for (int mf = 0; mf < 2; mf++) mma_bf16(acc[mf][nf], a[mf], b);
            }
        }
        __syncthreads();
    }

#pragma unroll
    for (int mf = 0; mf < 2; mf++)
#pragma unroll
        for (int nf = 0; nf < 8; nf++) {
            const int c = nw * 64 + nf * 8 + 2 * tg;
            if (c >= NOUT) continue;
#pragma unroll
            for (int half = 0; half < 2; half++) {
                size_t R = R0 + mw * 32 + mf * 16 + gr + half * 8;
                int t = (int)(R >> 9);
                int b = (int)(R & 511);
                if (b < BATCH) {
                    float* dst = out + ((size_t)b * TSTEPS + t) * NOUT + c;
                    dst[0] = fast_sigmoid(acc[mf][nf][half * 2 + 0] + bfc[c]);
                    dst[1] = fast_sigmoid(acc[mf][nf][half * 2 + 1] + bfc[c + 1]);
                }
            }
        }
}

// -------------------------------------------------------------------------
extern "C" void kernel_launch(void* const* d_in, const int* in_sizes, int n_in,
                              void* d_out, int out_size) {
    const float* inp  = (const float*)d_in[0];
    const float* Wih  = (const float*)d_in[1];
    const float* Whh  = (const float*)d_in[2];
    const float* bih  = (const float*)d_in[3];
    const float* bhh  = (const float*)d_in[4];
    const float* Wfc  = (const float*)d_in[5];
    const float* bfc  = (const float*)d_in[6];
    float* out = (float*)d_out;

    cudaFuncSetAttribute(lstm_persist_kernel,
                         cudaFuncAttributeMaxDynamicSharedMemorySize, PERSIST_SMEM);
    cudaFuncSetAttribute(xg_gemm_kernel,
                         cudaFuncAttributeMaxDynamicSharedMemorySize, XG_SMEM);

    zero_state_kernel<<<1, 32>>>();
    {
        long long total = (long long)TSTEPS * BATCH * EMB;
        int blocks = (int)((total + 255) / 256);
        prep_xbf_kernel<<<blocks, 256>>>(inp);
    }
    zero_xbf_pad_kernel<<<(TSTEPS * 12 * EMB / 2 + 255) / 256, 256>>>();
    prep_w_kernel<<<(2048 * 1024) / 256, 256>>>(Wih, Whh, bih, bhh, Wfc);

    xg_gemm_kernel<<<dim3(16, MROWS / 128), 256, XG_SMEM>>>();

    lstm_persist_kernel<<<dim3(4, 32), 256, PERSIST_SMEM>>>();

    fc_gemm_kernel<<<1024, 256>>>(bfc, out);
}